// round 1
// baseline (speedup 1.0000x reference)
#include <cuda_runtime.h>
#include <math.h>

#define NN 50000
#define EE 1600000
#define GG 64
#define HID 64
#define NH 4
#define CH 16
#define NIN 32
#define EIN 16

// ---------------- scratch (device globals; no allocation allowed) ----------
__device__ __align__(16) float    g_h[NN * HID];
__device__ __align__(16) float    g_q[NN * HID];
__device__ __align__(16) float    g_k[NN * HID];
__device__ __align__(16) float    g_v[NN * HID];
__device__ __align__(16) float    g_skip[NN * HID];
__device__ __align__(16) float    g_qe[NN * HID];
__device__ __align__(16) float    g_agg[NN * HID];
__device__ __align__(16) float    g_alpha[EE * NH];
__device__ __align__(16) unsigned g_amax[NN * NH];
__device__ __align__(16) float    g_denom[NN * NH];
__device__ __align__(16) float    g_pool[GG * HID];
__device__ __align__(16) float    g_cnt[GG];

// ---------------- helpers ---------------------------------------------------
__device__ __forceinline__ unsigned fenc(float f) {
    unsigned u = __float_as_uint(f);
    return (u & 0x80000000u) ? ~u : (u | 0x80000000u);
}
__device__ __forceinline__ float fdec(unsigned u) {
    return (u & 0x80000000u) ? __uint_as_float(u ^ 0x80000000u)
                             : __uint_as_float(~u);
}
#define AMAX_INIT 0x007fffffu   /* fenc(-inf) */

__device__ __forceinline__ void red_add_v4(float* p, float4 v) {
    asm volatile("red.global.add.v4.f32 [%0], {%1,%2,%3,%4};"
                 :: "l"(p), "f"(v.x), "f"(v.y), "f"(v.z), "f"(v.w) : "memory");
}
__device__ __forceinline__ void red_add_f(float* p, float v) {
    asm volatile("red.global.add.f32 [%0], %1;" :: "l"(p), "f"(v) : "memory");
}

// ---------------- input layer: h = relu(x @ Wn + bn) ------------------------
__global__ void k_input(const float* __restrict__ x,
                        const float* __restrict__ Wn,
                        const float* __restrict__ bn) {
    __shared__ float sW[NIN * HID];     // 8KB
    __shared__ float sx[16][NIN + 2];
    __shared__ float sb[HID];
    int t = threadIdx.x;
    for (int i = t; i < NIN * HID; i += 256) sW[i] = Wn[i];
    if (t < HID) sb[t] = bn[t];
    int nb = blockIdx.x * 16;
    for (int i = t; i < 16 * NIN; i += 256) {
        int r = i / NIN, c = i % NIN, n = nb + r;
        sx[r][c] = (n < NN) ? x[n * NIN + c] : 0.f;
    }
    __syncthreads();
    int cw = t & 15;      // 4-col group
    int r  = t >> 4;      // node row 0..15
    int n  = nb + r;
    float a0 = sb[cw*4], a1 = sb[cw*4+1], a2 = sb[cw*4+2], a3 = sb[cw*4+3];
#pragma unroll
    for (int i = 0; i < NIN; i++) {
        float hv = sx[r][i];
        float4 w = *(const float4*)&sW[i * HID + cw * 4];
        a0 += hv * w.x; a1 += hv * w.y; a2 += hv * w.z; a3 += hv * w.w;
    }
    if (n < NN) {
        float4 o = make_float4(fmaxf(a0,0.f), fmaxf(a1,0.f), fmaxf(a2,0.f), fmaxf(a3,0.f));
        *(float4*)&g_h[n * HID + cw * 4] = o;
    }
}

// ---------------- per-layer node linears: q,k,v,skip + init amax/denom/agg --
// dynamic smem: sW[4*4096] + sb[256] + sh[16*68]
__global__ void k_qkvs(const float* __restrict__ Wq, const float* __restrict__ bq,
                       const float* __restrict__ Wk, const float* __restrict__ bk,
                       const float* __restrict__ Wv, const float* __restrict__ bv,
                       const float* __restrict__ Ws, const float* __restrict__ bs) {
    extern __shared__ float sm[];
    float* sW = sm;                   // 4*4096
    float* sb = sm + 4 * 4096;        // 256
    float* sh = sb + 256;             // 16*68
    int t = threadIdx.x;
    const float* Wp[4] = {Wq, Wk, Wv, Ws};
    const float* bp[4] = {bq, bk, bv, bs};
#pragma unroll
    for (int a = 0; a < 4; a++)
        for (int i = t; i < 4096; i += 256) sW[a * 4096 + i] = Wp[a][i];
    sb[t] = bp[t >> 6][t & 63];
    int nb = blockIdx.x * 16;
    for (int i = t; i < 16 * HID; i += 256) {
        int r = i >> 6, c = i & 63, n = nb + r;
        sh[r * 68 + c] = (n < NN) ? g_h[n * HID + c] : 0.f;
    }
    __syncthreads();
    int a  = t >> 6;          // which output array
    int cw = t & 15;          // 4-col group
    int nq = (t >> 4) & 3;    // node quarter (4 nodes)
    float acc[4][4];
#pragma unroll
    for (int m = 0; m < 4; m++)
#pragma unroll
        for (int j = 0; j < 4; j++) acc[m][j] = sb[a * 64 + cw * 4 + j];
    const float* w = &sW[a * 4096 + cw * 4];
#pragma unroll 8
    for (int i = 0; i < HID; i++) {
        float4 wv = *(const float4*)&w[i * 64];
#pragma unroll
        for (int m = 0; m < 4; m++) {
            float hv = sh[(nq * 4 + m) * 68 + i];
            acc[m][0] += hv * wv.x; acc[m][1] += hv * wv.y;
            acc[m][2] += hv * wv.z; acc[m][3] += hv * wv.w;
        }
    }
    float* outp = (a == 0) ? g_q : (a == 1) ? g_k : (a == 2) ? g_v : g_skip;
#pragma unroll
    for (int m = 0; m < 4; m++) {
        int n = nb + nq * 4 + m;
        if (n < NN)
            *(float4*)&outp[n * HID + cw * 4] =
                make_float4(acc[m][0], acc[m][1], acc[m][2], acc[m][3]);
    }
    // zero/init per-layer accumulators for these nodes
    for (int i = t; i < 16 * HID; i += 256) {
        int n = nb + (i >> 6);
        if (n < NN) g_agg[n * HID + (i & 63)] = 0.f;
    }
    for (int i = t; i < 16 * NH; i += 256) {
        int n = nb + (i >> 2);
        if (n < NN) { g_denom[n * NH + (i & 3)] = 0.f; g_amax[n * NH + (i & 3)] = AMAX_INIT; }
    }
}

// ---------------- qe[n, h*16+i] = sum_c We[i, h*16+c] * q[n, h*16+c] --------
__global__ void k_qe(const float* __restrict__ We) {
    __shared__ float sWe[EIN * HID];   // 4KB
    __shared__ float sq[4][HID];
    int t = threadIdx.x;
    for (int i = t; i < EIN * HID; i += 256) sWe[i] = We[i];
    int nb = blockIdx.x * 4;
    for (int i = t; i < 4 * HID; i += 256) {
        int r = i >> 6, n = nb + r;
        sq[r][i & 63] = (n < NN) ? g_q[n * HID + (i & 63)] : 0.f;
    }
    __syncthreads();
    int r = t >> 6, j = t & 63, h = j >> 4, i0 = j & 15;
    int n = nb + r;
    float s = 0.f;
#pragma unroll
    for (int c = 0; c < CH; c++)
        s += sWe[i0 * HID + h * CH + c] * sq[r][h * CH + c];
    if (n < NN) g_qe[n * HID + j] = s;
}

// ---------------- edge pass 1: alpha + segment max (4 threads / edge) -------
__global__ void k_pass1(const int* __restrict__ ei, const float* __restrict__ ea) {
    long tid = (long)blockIdx.x * 256 + threadIdx.x;
    long e = tid >> 2;
    int  h = (int)(tid & 3);
    if (e >= EE) return;
    int s = ei[e];
    int d = ei[EE + e];
    const float4* qp  = (const float4*)&g_q [(size_t)d * HID + h * CH];
    const float4* kp  = (const float4*)&g_k [(size_t)s * HID + h * CH];
    const float4* qep = (const float4*)&g_qe[(size_t)d * HID + h * CH];
    const float4* eap = (const float4*)&ea[(size_t)e * EIN];
    float acc = 0.f;
#pragma unroll
    for (int g4 = 0; g4 < 4; g4++) {
        float4 qv = qp[g4], kv = kp[g4], qev = qep[g4], eav = eap[g4];
        acc += qv.x * kv.x + qv.y * kv.y + qv.z * kv.z + qv.w * kv.w;
        acc += eav.x * qev.x + eav.y * qev.y + eav.z * qev.z + eav.w * qev.w;
    }
    acc *= 0.25f;  // 1/sqrt(C), C=16
    g_alpha[e * NH + h] = acc;
    atomicMax(&g_amax[d * NH + h], fenc(acc));
}

// ---------------- edge pass 2: exp + denom + weighted V aggregate -----------
__global__ void k_pass2(const int* __restrict__ ei, const float* __restrict__ ea,
                        const float* __restrict__ We) {
    __shared__ float sWe[EIN * HID];
    int t = threadIdx.x;
    for (int i = t; i < EIN * HID; i += 256) sWe[i] = We[i];
    __syncthreads();
    long tid = (long)blockIdx.x * 256 + t;
    long e = tid >> 2;
    int  h = (int)(tid & 3);
    if (e >= EE) return;
    int s = ei[e];
    int d = ei[EE + e];
    float al = g_alpha[e * NH + h];
    float am = fdec(g_amax[d * NH + h]);
    float ex = __expf(al - am);
    red_add_f(&g_denom[d * NH + h], ex);
    float eav[EIN];
#pragma unroll
    for (int i = 0; i < 4; i++) {
        float4 v4 = ((const float4*)&ea[(size_t)e * EIN])[i];
        eav[i*4] = v4.x; eav[i*4+1] = v4.y; eav[i*4+2] = v4.z; eav[i*4+3] = v4.w;
    }
#pragma unroll
    for (int g4 = 0; g4 < 4; g4++) {
        int col = h * CH + g4 * 4;
        float4 vv = *(const float4*)&g_v[(size_t)s * HID + col];
        float e0 = 0.f, e1 = 0.f, e2 = 0.f, e3 = 0.f;
#pragma unroll
        for (int i = 0; i < EIN; i++) {
            float a = eav[i];
            float4 wr = *(const float4*)&sWe[i * HID + col];
            e0 += a * wr.x; e1 += a * wr.y; e2 += a * wr.z; e3 += a * wr.w;
        }
        float4 o = make_float4(ex * (vv.x + e0), ex * (vv.y + e1),
                               ex * (vv.z + e2), ex * (vv.w + e3));
        red_add_v4(&g_agg[(size_t)d * HID + col], o);
    }
}

// ---------------- node update: h += relu(agg/denom + skip) ------------------
__global__ void k_update() {
    long idx = (long)blockIdx.x * 256 + threadIdx.x;   // (n, colgroup)
    int n = (int)(idx >> 4), cg = (int)(idx & 15);
    if (n >= NN) return;
    int col = cg * 4, h = col >> 4;
    float inv = 1.f / (g_denom[n * NH + h] + 1e-16f);
    float4 ag = *(const float4*)&g_agg [n * HID + col];
    float4 sk = *(const float4*)&g_skip[n * HID + col];
    float4 hv = *(float4*)&g_h[n * HID + col];
    hv.x += fmaxf(ag.x * inv + sk.x, 0.f);
    hv.y += fmaxf(ag.y * inv + sk.y, 0.f);
    hv.z += fmaxf(ag.z * inv + sk.z, 0.f);
    hv.w += fmaxf(ag.w * inv + sk.w, 0.f);
    *(float4*)&g_h[n * HID + col] = hv;
}

// ---------------- pooling + MLP ---------------------------------------------
__global__ void k_poolzero() {
    int t = threadIdx.x;
    for (int i = t; i < GG * HID; i += 256) g_pool[i] = 0.f;
    if (t < GG) g_cnt[t] = 0.f;
}

__global__ void k_pool(const int* __restrict__ batch) {
    long idx = (long)blockIdx.x * 256 + threadIdx.x;
    int n = (int)(idx >> 4), cg = (int)(idx & 15);
    if (n >= NN) return;
    int b = batch[n];
    float4 hv = *(const float4*)&g_h[n * HID + cg * 4];
    red_add_v4(&g_pool[b * HID + cg * 4], hv);
    if (cg == 0) red_add_f(&g_cnt[b], 1.f);
}

__global__ void k_mlp(const float* __restrict__ W1, const float* __restrict__ b1,
                      const float* __restrict__ W2, const float* __restrict__ b2,
                      float* __restrict__ out) {
    __shared__ float sm[HID];
    int g = blockIdx.x, t = threadIdx.x;   // 64 threads
    float cnt = fmaxf(g_cnt[g], 1.f);
    sm[t] = g_pool[g * HID + t] / cnt;
    __syncthreads();
    if (t < 32) {
        float r = b1[t];
#pragma unroll
        for (int i = 0; i < HID; i++) r += sm[i] * W1[i * 32 + t];
        r = fmaxf(r, 0.f) * W2[t];
#pragma unroll
        for (int o = 16; o; o >>= 1) r += __shfl_down_sync(0xffffffffu, r, o);
        if (t == 0) out[g] = r + b2[0];
    }
}

// ---------------- launch ----------------------------------------------------
extern "C" void kernel_launch(void* const* d_in, const int* in_sizes, int n_in,
                              void* d_out, int out_size) {
    const float* x   = (const float*)d_in[0];
    const int*   ei  = (const int*)d_in[1];
    const float* ea  = (const float*)d_in[2];
    const int*   bat = (const int*)d_in[3];
    const float* Wn  = (const float*)d_in[4];
    const float* bn  = (const float*)d_in[5];
    const float* Wq  = (const float*)d_in[6];
    const float* bq  = (const float*)d_in[7];
    const float* Wk  = (const float*)d_in[8];
    const float* bk  = (const float*)d_in[9];
    const float* Wv  = (const float*)d_in[10];
    const float* bv  = (const float*)d_in[11];
    const float* We  = (const float*)d_in[12];
    const float* Ws  = (const float*)d_in[13];
    const float* bs  = (const float*)d_in[14];
    const float* W1  = (const float*)d_in[15];
    const float* b1  = (const float*)d_in[16];
    const float* W2  = (const float*)d_in[17];
    const float* b2  = (const float*)d_in[18];
    float* out = (float*)d_out;

    const int QKVS_SMEM = (4 * 4096 + 256 + 16 * 68) * (int)sizeof(float);  // 70912
    cudaFuncSetAttribute(k_qkvs, cudaFuncAttributeMaxDynamicSharedMemorySize, QKVS_SMEM);

    const int NODE_BLOCKS = (NN + 15) / 16;        // 3125
    const int EDGE_BLOCKS = (4 * EE + 255) / 256;  // 25000

    k_input<<<NODE_BLOCKS, 256>>>(x, Wn, bn);
    for (int l = 0; l < 3; l++) {
        k_qkvs<<<NODE_BLOCKS, 256, QKVS_SMEM>>>(
            Wq + l * HID * HID, bq + l * HID,
            Wk + l * HID * HID, bk + l * HID,
            Wv + l * HID * HID, bv + l * HID,
            Ws + l * HID * HID, bs + l * HID);
        k_qe<<<(NN + 3) / 4, 256>>>(We + l * EIN * HID);
        k_pass1<<<EDGE_BLOCKS, 256>>>(ei, ea);
        k_pass2<<<EDGE_BLOCKS, 256>>>(ei, ea, We + l * EIN * HID);
        k_update<<<NODE_BLOCKS, 256>>>();
    }
    k_poolzero<<<1, 256>>>();
    k_pool<<<NODE_BLOCKS, 256>>>(bat);
    k_mlp<<<GG, 64>>>(W1, b1, W2, b2, out);
}

// round 3
// speedup vs baseline: 1.9632x; 1.9632x over previous
#include <cuda_runtime.h>
#include <math.h>

#define NN 50000
#define EE 1600000
#define GG 64
#define HID 64
#define NH 4
#define CH 16
#define NIN 32
#define EIN 16

// ---------------- scratch (device globals; no allocation allowed) ----------
__device__ __align__(16) float g_h[NN * HID];
__device__ __align__(16) float g_q[NN * HID];
__device__ __align__(16) float g_k[NN * HID];
__device__ __align__(16) float g_v[NN * HID];
__device__ __align__(16) float g_skip[NN * HID];
__device__ __align__(16) float g_qe[NN * HID];
__device__ __align__(16) float g_eas[(size_t)EE * EIN];   // ea permuted to dst-sorted order
__device__ int   g_src[EE];        // src node per sorted edge
__device__ int   g_deg[NN];
__device__ int   g_off[NN + 1];
__device__ int   g_ctr[NN];
__device__ __align__(16) float g_pool[GG * HID];
__device__ float g_cnt[GG];

__device__ __forceinline__ void red_add_v4(float* p, float4 v) {
    asm volatile("red.global.add.v4.f32 [%0], {%1,%2,%3,%4};"
                 :: "l"(p), "f"(v.x), "f"(v.y), "f"(v.z), "f"(v.w) : "memory");
}
__device__ __forceinline__ void red_add_f(float* p, float v) {
    asm volatile("red.global.add.f32 [%0], %1;" :: "l"(p), "f"(v) : "memory");
}

// ---------------- input layer: h = relu(x @ Wn + bn) ------------------------
__global__ void k_input(const float* __restrict__ x,
                        const float* __restrict__ Wn,
                        const float* __restrict__ bn) {
    __shared__ float sW[NIN * HID];
    __shared__ float sx[16][NIN + 2];
    __shared__ float sb[HID];
    int t = threadIdx.x;
    for (int i = t; i < NIN * HID; i += 256) sW[i] = Wn[i];
    if (t < HID) sb[t] = bn[t];
    int nb = blockIdx.x * 16;
    for (int i = t; i < 16 * NIN; i += 256) {
        int r = i / NIN, c = i % NIN, n = nb + r;
        sx[r][c] = (n < NN) ? x[n * NIN + c] : 0.f;
    }
    __syncthreads();
    int cw = t & 15;
    int r  = t >> 4;
    int n  = nb + r;
    float a0 = sb[cw*4], a1 = sb[cw*4+1], a2 = sb[cw*4+2], a3 = sb[cw*4+3];
#pragma unroll
    for (int i = 0; i < NIN; i++) {
        float hv = sx[r][i];
        float4 w = *(const float4*)&sW[i * HID + cw * 4];
        a0 += hv * w.x; a1 += hv * w.y; a2 += hv * w.z; a3 += hv * w.w;
    }
    if (n < NN) {
        float4 o = make_float4(fmaxf(a0,0.f), fmaxf(a1,0.f), fmaxf(a2,0.f), fmaxf(a3,0.f));
        *(float4*)&g_h[n * HID + cw * 4] = o;
    }
}

// ---------------- CSR sort by dst -------------------------------------------
__global__ void k_zerodeg() {
    int i = blockIdx.x * 256 + threadIdx.x;
    if (i < NN) g_deg[i] = 0;
}
__global__ void k_hist(const int* __restrict__ ei) {
    int e = blockIdx.x * 256 + threadIdx.x;   // grid sized exactly EE
    atomicAdd(&g_deg[ei[EE + e]], 1);
}
__global__ void k_scan() {
    __shared__ int sp[1024];
    int t = threadIdx.x;
    const int CHK = (NN + 1023) / 1024;   // 49
    int beg = t * CHK, fin = min(beg + CHK, NN);
    int s = 0;
    for (int i = beg; i < fin; i++) s += g_deg[i];
    sp[t] = s; __syncthreads();
    for (int off = 1; off < 1024; off <<= 1) {
        int v = (t >= off) ? sp[t - off] : 0;
        __syncthreads();
        sp[t] += v;
        __syncthreads();
    }
    int run = sp[t] - s;   // exclusive
    for (int i = beg; i < fin; i++) {
        g_off[i] = run; g_ctr[i] = run; run += g_deg[i];
    }
    if (t == 1023) g_off[NN] = EE;
}
__global__ void k_scatter(const int* __restrict__ ei, const float* __restrict__ ea) {
    long tid = (long)blockIdx.x * 256 + threadIdx.x;  // grid = EE*4/256 exactly
    long e = tid >> 2;
    int  j = (int)(tid & 3);
    int lane = threadIdx.x & 31;
    int pos = 0;
    if (j == 0) {
        int d = ei[EE + e];
        pos = atomicAdd(&g_ctr[d], 1);
        g_src[pos] = ei[e];
    }
    pos = __shfl_sync(0xffffffffu, pos, lane & ~3);
    float4 v = ((const float4*)&ea[(size_t)e * EIN])[j];
    ((float4*)&g_eas[(size_t)pos * EIN])[j] = v;
}

// ---------------- per-layer node linears: q,k,v,skip ------------------------
__global__ void k_qkvs(const float* __restrict__ Wq, const float* __restrict__ bq,
                       const float* __restrict__ Wk, const float* __restrict__ bk,
                       const float* __restrict__ Wv, const float* __restrict__ bv,
                       const float* __restrict__ Ws, const float* __restrict__ bs) {
    extern __shared__ float sm[];
    float* sW = sm;                   // 4*4096
    float* sb = sm + 4 * 4096;        // 256
    float* sh = sb + 256;             // 16*68
    int t = threadIdx.x;
    const float* Wp[4] = {Wq, Wk, Wv, Ws};
    const float* bp[4] = {bq, bk, bv, bs};
#pragma unroll
    for (int a = 0; a < 4; a++)
        for (int i = t; i < 4096; i += 256) sW[a * 4096 + i] = Wp[a][i];
    sb[t] = bp[t >> 6][t & 63];
    int nb = blockIdx.x * 16;
    for (int i = t; i < 16 * HID; i += 256) {
        int r = i >> 6, c = i & 63, n = nb + r;
        sh[r * 68 + c] = (n < NN) ? g_h[n * HID + c] : 0.f;
    }
    __syncthreads();
    int a  = t >> 6;
    int cw = t & 15;
    int nq = (t >> 4) & 3;
    float acc[4][4];
#pragma unroll
    for (int m = 0; m < 4; m++)
#pragma unroll
        for (int j = 0; j < 4; j++) acc[m][j] = sb[a * 64 + cw * 4 + j];
    const float* w = &sW[a * 4096 + cw * 4];
#pragma unroll 8
    for (int i = 0; i < HID; i++) {
        float4 wv = *(const float4*)&w[i * 64];
#pragma unroll
        for (int m = 0; m < 4; m++) {
            float hv = sh[(nq * 4 + m) * 68 + i];
            acc[m][0] += hv * wv.x; acc[m][1] += hv * wv.y;
            acc[m][2] += hv * wv.z; acc[m][3] += hv * wv.w;
        }
    }
    float* outp = (a == 0) ? g_q : (a == 1) ? g_k : (a == 2) ? g_v : g_skip;
#pragma unroll
    for (int m = 0; m < 4; m++) {
        int n = nb + nq * 4 + m;
        if (n < NN)
            *(float4*)&outp[n * HID + cw * 4] =
                make_float4(acc[m][0], acc[m][1], acc[m][2], acc[m][3]);
    }
}

// ---------------- qe[n, h*16+i] = sum_c We[i, h*16+c] * q[n, h*16+c] --------
__global__ void k_qe(const float* __restrict__ We) {
    __shared__ float sWe[EIN * HID];
    __shared__ float sq[4][HID];
    int t = threadIdx.x;
    for (int i = t; i < EIN * HID; i += 256) sWe[i] = We[i];
    int nb = blockIdx.x * 4;
    for (int i = t; i < 4 * HID; i += 256) {
        int r = i >> 6, n = nb + r;
        sq[r][i & 63] = (n < NN) ? g_q[n * HID + (i & 63)] : 0.f;
    }
    __syncthreads();
    int r = t >> 6, j = t & 63, h = j >> 4, i0 = j & 15;
    int n = nb + r;
    float s = 0.f;
#pragma unroll
    for (int c = 0; c < CH; c++)
        s += sWe[i0 * HID + h * CH + c] * sq[r][h * CH + c];
    if (n < NN) g_qe[n * HID + j] = s;
}

// ---------------- fused edge pass: online softmax + aggregate + update ------
// warp per dst node; 8 groups of 4 lanes, one edge per group per iteration.
// WARP-UNIFORM trip count (nIter) so all shfl_sync stay convergent.
__global__ void __launch_bounds__(256, 2) k_edge(const float* __restrict__ We) {
    __shared__ float sWe[EIN * HID];
    __shared__ float s_vacc[8][68];
    __shared__ float s_t[8][68];
    __shared__ float s_den[8][4];
    int t = threadIdx.x;
    for (int i = t; i < EIN * HID; i += 256) sWe[i] = We[i];
    __syncthreads();
    int wid = t >> 5, lane = t & 31;
    int n = blockIdx.x * 8 + wid;          // grid = 6250, exact
    int g = lane >> 2, j = lane & 3;
    int begin = g_off[n], end = g_off[n + 1];
    int nIter = (end - begin + 7) >> 3;    // uniform across the warp

    float qv[4][4], qev[4][4];
    const float4* qp  = (const float4*)&g_q [(size_t)n * HID];
    const float4* qep = (const float4*)&g_qe[(size_t)n * HID];
#pragma unroll
    for (int tt = 0; tt < 4; tt++) {
        float4 a = qp [tt * 4 + j];
        qv [tt][0] = a.x; qv [tt][1] = a.y; qv [tt][2] = a.z; qv [tt][3] = a.w;
        float4 b = qep[tt * 4 + j];
        qev[tt][0] = b.x; qev[tt][1] = b.y; qev[tt][2] = b.z; qev[tt][3] = b.w;
    }

    float m[4]   = {-1e30f, -1e30f, -1e30f, -1e30f};
    float den[4] = {0.f, 0.f, 0.f, 0.f};
    float vacc[4][4] = {};
    float eacc[4][4] = {};

    for (int it = 0; it < nIter; it++) {
        int pos = begin + it * 8 + g;
        bool valid = pos < end;
        int pc = valid ? pos : begin;       // clamp for safe loads
        int s = g_src[pc];
        float4 eaq = ((const float4*)&g_eas[(size_t)pc * EIN])[j];
        float eav[4] = {eaq.x, eaq.y, eaq.z, eaq.w};
        const float4* kp = (const float4*)&g_k[(size_t)s * HID];
        const float4* vp = (const float4*)&g_v[(size_t)s * HID];
        float4 kq[4], vq[4];
#pragma unroll
        for (int tt = 0; tt < 4; tt++) { kq[tt] = kp[tt * 4 + j]; vq[tt] = vp[tt * 4 + j]; }
        float p[4];
#pragma unroll
        for (int tt = 0; tt < 4; tt++) {
            p[tt] = qv[tt][0]*kq[tt].x + qv[tt][1]*kq[tt].y
                  + qv[tt][2]*kq[tt].z + qv[tt][3]*kq[tt].w
                  + qev[tt][0]*eav[0] + qev[tt][1]*eav[1]
                  + qev[tt][2]*eav[2] + qev[tt][3]*eav[3];
        }
#pragma unroll
        for (int off = 1; off <= 2; off <<= 1)
#pragma unroll
            for (int tt = 0; tt < 4; tt++)
                p[tt] += __shfl_xor_sync(0xffffffffu, p[tt], off);
        if (valid) {
#pragma unroll
            for (int tt = 0; tt < 4; tt++) {
                float alpha = p[tt] * 0.25f;
                float nm = fmaxf(m[tt], alpha);
                float sc = __expf(m[tt] - nm);
                float ex = __expf(alpha - nm);
                m[tt] = nm;
                den[tt] = den[tt] * sc + ex;
                vacc[tt][0] = vacc[tt][0] * sc + ex * vq[tt].x;
                vacc[tt][1] = vacc[tt][1] * sc + ex * vq[tt].y;
                vacc[tt][2] = vacc[tt][2] * sc + ex * vq[tt].z;
                vacc[tt][3] = vacc[tt][3] * sc + ex * vq[tt].w;
#pragma unroll
                for (int c = 0; c < 4; c++)
                    eacc[tt][c] = eacc[tt][c] * sc + ex * eav[c];
            }
        }
    }

    // merge the 8 groups (online-softmax merge, butterfly over lanes)
#pragma unroll
    for (int off = 4; off <= 16; off <<= 1) {
#pragma unroll
        for (int tt = 0; tt < 4; tt++) {
            float m2 = __shfl_xor_sync(0xffffffffu, m[tt], off);
            float d2 = __shfl_xor_sync(0xffffffffu, den[tt], off);
            float nm = fmaxf(m[tt], m2);
            float s1 = __expf(m[tt] - nm);
            float s2 = __expf(m2 - nm);
            den[tt] = den[tt] * s1 + d2 * s2;
#pragma unroll
            for (int c = 0; c < 4; c++) {
                float v2 = __shfl_xor_sync(0xffffffffu, vacc[tt][c], off);
                vacc[tt][c] = vacc[tt][c] * s1 + v2 * s2;
                float e2 = __shfl_xor_sync(0xffffffffu, eacc[tt][c], off);
                eacc[tt][c] = eacc[tt][c] * s1 + e2 * s2;
            }
            m[tt] = nm;
        }
    }

    if (g == 0) {
#pragma unroll
        for (int tt = 0; tt < 4; tt++) {
#pragma unroll
            for (int c = 0; c < 4; c++) {
                s_vacc[wid][tt * 16 + 4 * j + c] = vacc[tt][c];
                s_t   [wid][tt * 16 + 4 * j + c] = eacc[tt][c];
            }
            if (j == 0) s_den[wid][tt] = den[tt];
        }
    }
    __syncwarp();

#pragma unroll
    for (int u = 0; u < 2; u++) {
        int col = lane * 2 + u;
        int hh = col >> 4;
        float inv = 1.f / (s_den[wid][hh] + 1e-16f);
        float et = 0.f;
#pragma unroll
        for (int i = 0; i < EIN; i++)
            et += s_t[wid][hh * 16 + i] * sWe[i * HID + col];
        float val = (s_vacc[wid][col] + et) * inv;
        float sk = g_skip[(size_t)n * HID + col];
        float hv = g_h[(size_t)n * HID + col];
        g_h[(size_t)n * HID + col] = hv + fmaxf(val + sk, 0.f);
    }
}

// ---------------- pooling + MLP ---------------------------------------------
__global__ void k_poolzero() {
    int t = threadIdx.x;
    for (int i = t; i < GG * HID; i += 256) g_pool[i] = 0.f;
    if (t < GG) g_cnt[t] = 0.f;
}
__global__ void k_pool(const int* __restrict__ batch) {
    long idx = (long)blockIdx.x * 256 + threadIdx.x;
    int n = (int)(idx >> 4), cg = (int)(idx & 15);
    if (n >= NN) return;
    int b = batch[n];
    float4 hv = *(const float4*)&g_h[n * HID + cg * 4];
    red_add_v4(&g_pool[b * HID + cg * 4], hv);
    if (cg == 0) red_add_f(&g_cnt[b], 1.f);
}
__global__ void k_mlp(const float* __restrict__ W1, const float* __restrict__ b1,
                      const float* __restrict__ W2, const float* __restrict__ b2,
                      float* __restrict__ out) {
    __shared__ float sm[HID];
    int g = blockIdx.x, t = threadIdx.x;
    float cnt = fmaxf(g_cnt[g], 1.f);
    sm[t] = g_pool[g * HID + t] / cnt;
    __syncthreads();
    if (t < 32) {
        float r = b1[t];
#pragma unroll
        for (int i = 0; i < HID; i++) r += sm[i] * W1[i * 32 + t];
        r = fmaxf(r, 0.f) * W2[t];
#pragma unroll
        for (int o = 16; o; o >>= 1) r += __shfl_down_sync(0xffffffffu, r, o);
        if (t == 0) out[g] = r + b2[0];
    }
}

// ---------------- launch ----------------------------------------------------
extern "C" void kernel_launch(void* const* d_in, const int* in_sizes, int n_in,
                              void* d_out, int out_size) {
    const float* x   = (const float*)d_in[0];
    const int*   ei  = (const int*)d_in[1];
    const float* ea  = (const float*)d_in[2];
    const int*   bat = (const int*)d_in[3];
    const float* Wn  = (const float*)d_in[4];
    const float* bn  = (const float*)d_in[5];
    const float* Wq  = (const float*)d_in[6];
    const float* bq  = (const float*)d_in[7];
    const float* Wk  = (const float*)d_in[8];
    const float* bk  = (const float*)d_in[9];
    const float* Wv  = (const float*)d_in[10];
    const float* bv  = (const float*)d_in[11];
    const float* We  = (const float*)d_in[12];
    const float* Ws  = (const float*)d_in[13];
    const float* bs  = (const float*)d_in[14];
    const float* W1  = (const float*)d_in[15];
    const float* b1  = (const float*)d_in[16];
    const float* W2  = (const float*)d_in[17];
    const float* b2  = (const float*)d_in[18];
    float* out = (float*)d_out;

    const int QKVS_SMEM = (4 * 4096 + 256 + 16 * 68) * (int)sizeof(float);
    cudaFuncSetAttribute(k_qkvs, cudaFuncAttributeMaxDynamicSharedMemorySize, QKVS_SMEM);

    const int NODE_BLOCKS = (NN + 15) / 16;   // 3125
    const int EDGE1T      = EE / 256;         // 6250 (1 thread/edge)
    const int EDGE4T      = EE * 4 / 256;     // 25000 (4 threads/edge)

    // CSR sort (once per launch, reused by all 3 layers)
    k_zerodeg<<<(NN + 255) / 256, 256>>>();
    k_hist<<<EDGE1T, 256>>>(ei);
    k_scan<<<1, 1024>>>();
    k_scatter<<<EDGE4T, 256>>>(ei, ea);

    k_input<<<NODE_BLOCKS, 256>>>(x, Wn, bn);
    for (int l = 0; l < 3; l++) {
        k_qkvs<<<NODE_BLOCKS, 256, QKVS_SMEM>>>(
            Wq + l * HID * HID, bq + l * HID,
            Wk + l * HID * HID, bk + l * HID,
            Wv + l * HID * HID, bv + l * HID,
            Ws + l * HID * HID, bs + l * HID);
        k_qe<<<(NN + 3) / 4, 256>>>(We + l * EIN * HID);
        k_edge<<<NN / 8, 256>>>(We + l * EIN * HID);
    }
    k_poolzero<<<1, 256>>>();
    k_pool<<<NODE_BLOCKS, 256>>>(bat);
    k_mlp<<<GG, 64>>>(W1, b1, W2, b2, out);
}

// round 9
// speedup vs baseline: 2.4824x; 1.2645x over previous
#include <cuda_runtime.h>
#include <cuda_fp16.h>
#include <math.h>

#define NN 50000
#define EE 1600000
#define GG 64
#define HID 64
#define NH 4
#define CH 16
#define NIN 32
#define EIN 16

// ---------------- scratch (device globals; no allocation allowed) ----------
__device__ __align__(16) float  g_h[NN * HID];
__device__ __align__(16) float  g_q[NN * HID];
__device__ __align__(16) float  g_k[NN * HID];
__device__ __align__(16) float  g_v[NN * HID];
__device__ __align__(16) float  g_skip[NN * HID];
__device__ __align__(16) float  g_qe[NN * HID];
__device__ __align__(16) __half g_eash[(size_t)EE * EIN];   // ea, dst-sorted, fp16
__device__ int   g_src[EE];
__device__ int   g_deg[NN];
__device__ int   g_off[NN + 1];
__device__ int   g_ctr[NN];
__device__ int   g_part[256];
__device__ int   g_partpre[256];
__device__ __align__(16) float g_pool[GG * HID];
__device__ float g_cnt[GG];

__device__ __forceinline__ void red_add_v4(float* p, float4 v) {
    asm volatile("red.global.add.v4.f32 [%0], {%1,%2,%3,%4};"
                 :: "l"(p), "f"(v.x), "f"(v.y), "f"(v.z), "f"(v.w) : "memory");
}
__device__ __forceinline__ void red_add_f(float* p, float v) {
    asm volatile("red.global.add.f32 [%0], %1;" :: "l"(p), "f"(v) : "memory");
}
__device__ __forceinline__ void fma2(unsigned long long& d,
                                     unsigned long long a, unsigned long long b) {
    asm("fma.rn.f32x2 %0, %1, %2, %0;" : "+l"(d) : "l"(a), "l"(b));
}
__device__ __forceinline__ unsigned long long pack2(float lo, float hi) {
    unsigned long long r;
    asm("mov.b64 %0, {%1, %2};" : "=l"(r) : "f"(lo), "f"(hi));
    return r;
}
__device__ __forceinline__ float unpack_sum(unsigned long long v) {
    float lo, hi;
    asm("mov.b64 {%0, %1}, %2;" : "=f"(lo), "=f"(hi) : "l"(v));
    return lo + hi;
}

// ---------------- input layer: h = relu(x @ Wn + bn) ------------------------
__global__ void k_input(const float* __restrict__ x,
                        const float* __restrict__ Wn,
                        const float* __restrict__ bn) {
    __shared__ float sW[NIN * HID];
    __shared__ float sx[16][NIN + 2];
    __shared__ float sb[HID];
    int t = threadIdx.x;
    for (int i = t; i < NIN * HID; i += 256) sW[i] = Wn[i];
    if (t < HID) sb[t] = bn[t];
    int nb = blockIdx.x * 16;
    for (int i = t; i < 16 * NIN; i += 256) {
        int r = i / NIN, c = i % NIN;
        sx[r][c] = x[(nb + r) * NIN + c];
    }
    __syncthreads();
    int cw = t & 15;
    int r  = t >> 4;
    int n  = nb + r;
    float a0 = sb[cw*4], a1 = sb[cw*4+1], a2 = sb[cw*4+2], a3 = sb[cw*4+3];
#pragma unroll
    for (int i = 0; i < NIN; i++) {
        float hv = sx[r][i];
        float4 w = *(const float4*)&sW[i * HID + cw * 4];
        a0 += hv * w.x; a1 += hv * w.y; a2 += hv * w.z; a3 += hv * w.w;
    }
    float4 o = make_float4(fmaxf(a0,0.f), fmaxf(a1,0.f), fmaxf(a2,0.f), fmaxf(a3,0.f));
    *(float4*)&g_h[n * HID + cw * 4] = o;
}

// ---------------- CSR sort by dst -------------------------------------------
__global__ void k_zerodeg() {
    int i = blockIdx.x * 256 + threadIdx.x;
    if (i < NN) g_deg[i] = 0;
}
__global__ void k_hist(const int* __restrict__ ei) {
    int e = blockIdx.x * 256 + threadIdx.x;
    atomicAdd(&g_deg[ei[EE + e]], 1);
}
// block partial sums (196 blocks x 256)
__global__ void k_scanA() {
    __shared__ int sp[256];
    int t = threadIdx.x, i = blockIdx.x * 256 + t;
    int d = (i < NN) ? g_deg[i] : 0;
    sp[t] = d; __syncthreads();
    for (int off = 128; off; off >>= 1) {
        if (t < off) sp[t] += sp[t + off];
        __syncthreads();
    }
    if (t == 0) g_part[blockIdx.x] = sp[0];
}
__global__ void k_scanB(int nparts) {
    __shared__ int sp[256];
    int t = threadIdx.x;
    int v = (t < nparts) ? g_part[t] : 0;
    sp[t] = v; __syncthreads();
    for (int off = 1; off < 256; off <<= 1) {
        int u = (t >= off) ? sp[t - off] : 0;
        __syncthreads();
        sp[t] += u;
        __syncthreads();
    }
    g_partpre[t] = sp[t] - v;   // exclusive
}
__global__ void k_scanC() {
    __shared__ int sp[256];
    int t = threadIdx.x, b = blockIdx.x, i = b * 256 + t;
    int d = (i < NN) ? g_deg[i] : 0;
    sp[t] = d; __syncthreads();
    for (int off = 1; off < 256; off <<= 1) {
        int u = (t >= off) ? sp[t - off] : 0;
        __syncthreads();
        sp[t] += u;
        __syncthreads();
    }
    int off0 = g_partpre[b] + sp[t] - d;   // exclusive
    if (i < NN) { g_off[i] = off0; g_ctr[i] = off0; }
    if (b == 0 && t == 0) g_off[NN] = EE;
}
__global__ void k_scatter(const int* __restrict__ ei, const float* __restrict__ ea) {
    long tid = (long)blockIdx.x * 256 + threadIdx.x;
    long e = tid >> 2;
    int  j = (int)(tid & 3);
    int lane = threadIdx.x & 31;
    int pos = 0;
    if (j == 0) {
        int d = ei[EE + e];
        pos = atomicAdd(&g_ctr[d], 1);
        g_src[pos] = ei[e];
    }
    pos = __shfl_sync(0xffffffffu, pos, lane & ~3);
    float4 v = ((const float4*)&ea[(size_t)e * EIN])[j];
    __half2 p0 = __float22half2_rn(make_float2(v.x, v.y));
    __half2 p1 = __float22half2_rn(make_float2(v.z, v.w));
    size_t base = (size_t)pos * EIN + j * 4;
    *(__half2*)&g_eash[base]     = p0;
    *(__half2*)&g_eash[base + 2] = p1;
}

// ---------------- per-layer node linears: q,k,v,skip + qe (fused) -----------
// dyn smem: sW2[4*4096] (i-interleaved pairs) + sb[256] + sh[16*68] + sWe[1024]
__global__ void k_qkvs(const float* __restrict__ Wq, const float* __restrict__ bq,
                       const float* __restrict__ Wk, const float* __restrict__ bk,
                       const float* __restrict__ Wv, const float* __restrict__ bv,
                       const float* __restrict__ Ws, const float* __restrict__ bs,
                       const float* __restrict__ We) {
    extern __shared__ float sm[];
    float* sW2 = sm;                    // 16384 (also aliased as sq later)
    float* sb  = sm + 16384;            // 256
    float* sh  = sm + 16640;            // 16*68
    float* sWe = sm + 17728;            // 1024
    int t = threadIdx.x;
    const float* Wp[4] = {Wq, Wk, Wv, Ws};
    const float* bp[4] = {bq, bk, bv, bs};
#pragma unroll
    for (int a0 = 0; a0 < 4; a0++)
        for (int idx = t; idx < 4096; idx += 256) {
            int i = idx >> 6, c = idx & 63;
            sW2[a0 * 4096 + ((i >> 1) << 7) + (c << 1) + (i & 1)] = Wp[a0][idx];
        }
    sb[t] = bp[t >> 6][t & 63];
    for (int i = t; i < 1024; i += 256) sWe[i] = We[i];
    int nb = blockIdx.x * 16;
    for (int i = t; i < 16 * HID; i += 256) {
        int r = i >> 6, c = i & 63;
        sh[r * 68 + c] = g_h[(nb + r) * HID + c];
    }
    __syncthreads();

    int a  = t >> 6;          // array
    int cw = t & 15;          // 4-col group
    int nq = (t >> 4) & 3;    // 4-node group
    unsigned long long acc2[4][4];
#pragma unroll
    for (int m = 0; m < 4; m++)
#pragma unroll
        for (int c = 0; c < 4; c++)
            acc2[m][c] = pack2(sb[a * 64 + cw * 4 + c], 0.f);
    const float* wbase = &sW2[a * 4096 + cw * 8];
#pragma unroll 4
    for (int i2 = 0; i2 < 32; i2++) {
        ulonglong2 w01 = *(const ulonglong2*)&wbase[i2 * 128];
        ulonglong2 w23 = *(const ulonglong2*)&wbase[i2 * 128 + 4];
#pragma unroll
        for (int m = 0; m < 4; m++) {
            unsigned long long hv =
                *(const unsigned long long*)&sh[(nq * 4 + m) * 68 + i2 * 2];
            fma2(acc2[m][0], hv, w01.x);
            fma2(acc2[m][1], hv, w01.y);
            fma2(acc2[m][2], hv, w23.x);
            fma2(acc2[m][3], hv, w23.y);
        }
    }
    float* outp = (a == 0) ? g_q : (a == 1) ? g_k : (a == 2) ? g_v : g_skip;
    float o[4][4];
#pragma unroll
    for (int m = 0; m < 4; m++) {
#pragma unroll
        for (int c = 0; c < 4; c++) o[m][c] = unpack_sum(acc2[m][c]);
        *(float4*)&outp[(nb + nq * 4 + m) * HID + cw * 4] =
            make_float4(o[m][0], o[m][1], o[m][2], o[m][3]);
    }
    __syncthreads();
    // stage q into sq (alias sW2[0..1024)) for qe
    float* sq = sm;
    if (a == 0)
#pragma unroll
        for (int m = 0; m < 4; m++)
#pragma unroll
            for (int c = 0; c < 4; c++)
                sq[(nq * 4 + m) * 64 + cw * 4 + c] = o[m][c];
    __syncthreads();
    // qe[n, h*16+i0] = sum_c We[i0, h*16+c] * q[n, h*16+c]
#pragma unroll
    for (int kk = 0; kk < 4; kk++) {
        int oo = t + 256 * kk;
        int r = oo >> 6, j = oo & 63, h = j >> 4, i0 = j & 15;
        float s = 0.f;
#pragma unroll
        for (int c = 0; c < CH; c++)
            s += sWe[i0 * HID + h * CH + c] * sq[r * 64 + h * CH + c];
        g_qe[(nb + r) * HID + j] = s;
    }
}

// ---------------- fused edge pass: online softmax + aggregate + update ------
// warp per dst node; 4 edge-slots x 8 lanes. Lane u covers cols u*4..u*4+3
// (head u>>2) and cols 32+u*4.. (head 2+(u>>2)).
__device__ __forceinline__ void merge_grp(float& m, float& d, float4& v, float4& e, int off) {
    float m2 = __shfl_xor_sync(0xffffffffu, m, off);
    float d2 = __shfl_xor_sync(0xffffffffu, d, off);
    float4 v2, e2;
    v2.x = __shfl_xor_sync(0xffffffffu, v.x, off);
    v2.y = __shfl_xor_sync(0xffffffffu, v.y, off);
    v2.z = __shfl_xor_sync(0xffffffffu, v.z, off);
    v2.w = __shfl_xor_sync(0xffffffffu, v.w, off);
    e2.x = __shfl_xor_sync(0xffffffffu, e.x, off);
    e2.y = __shfl_xor_sync(0xffffffffu, e.y, off);
    e2.z = __shfl_xor_sync(0xffffffffu, e.z, off);
    e2.w = __shfl_xor_sync(0xffffffffu, e.w, off);
    float nm = fmaxf(m, m2);
    float s1 = __expf(m - nm), s2 = __expf(m2 - nm);
    d = d * s1 + d2 * s2;
    v.x = v.x * s1 + v2.x * s2; v.y = v.y * s1 + v2.y * s2;
    v.z = v.z * s1 + v2.z * s2; v.w = v.w * s1 + v2.w * s2;
    e.x = e.x * s1 + e2.x * s2; e.y = e.y * s1 + e2.y * s2;
    e.z = e.z * s1 + e2.z * s2; e.w = e.w * s1 + e2.w * s2;
    m = nm;
}

__global__ void __launch_bounds__(256, 3) k_edge(const float* __restrict__ We) {
    __shared__ float sWe[EIN * HID];
    __shared__ float s_e[8][4][16];
    __shared__ float s_den[8][4];
    int t = threadIdx.x;
    for (int i = t; i < EIN * HID; i += 256) sWe[i] = We[i];
    __syncthreads();
    int wid = t >> 5, lane = t & 31;
    int n = blockIdx.x * 8 + wid;     // grid = 6250, exact
    int g = lane >> 3, u = lane & 7;
    int hA = u >> 2;                   // 0/1 ; second head = hA+2
    int eoff = (u & 3) * 4;            // ea element offset for this lane
    int begin = g_off[n], end = g_off[n + 1];
    int nIter = (end - begin + 3) >> 2;

    const float4* qp  = (const float4*)&g_q [(size_t)n * HID];
    const float4* qep = (const float4*)&g_qe[(size_t)n * HID];
    float4 qA = qp[u],  qB = qp[8 + u];
    float4 qeA = qep[u], qeB = qep[8 + u];

    float mA = -1e30f, mB = -1e30f, dA = 0.f, dB = 0.f;
    float4 vaccA = {0,0,0,0}, vaccB = {0,0,0,0};
    float4 eaccA = {0,0,0,0}, eaccB = {0,0,0,0};

    for (int it = 0; it < nIter; it++) {
        int pos = begin + it * 4 + g;
        bool valid = pos < end;
        int pc = valid ? pos : begin;
        int s = g_src[pc];
        // ea (fp16, streamed): .cs (evict-streaming) so k/v stay in L2
        const uint2* ep = (const uint2*)&g_eash[(size_t)pc * EIN + eoff];
        uint2 rr = __ldcs(ep);
        __half2 h0 = *(__half2*)&rr.x, h1 = *(__half2*)&rr.y;
        float2 f0 = __half22float2(h0), f1 = __half22float2(h1);
        float4 eav = make_float4(f0.x, f0.y, f1.x, f1.y);

        const float4* kp = (const float4*)&g_k[(size_t)s * HID];
        const float4* vp = (const float4*)&g_v[(size_t)s * HID];
        float4 kA = kp[u], kB = kp[8 + u];
        float4 vA = vp[u], vB = vp[8 + u];
        float pA = qA.x*kA.x + qA.y*kA.y + qA.z*kA.z + qA.w*kA.w
                 + qeA.x*eav.x + qeA.y*eav.y + qeA.z*eav.z + qeA.w*eav.w;
        float pB = qB.x*kB.x + qB.y*kB.y + qB.z*kB.z + qB.w*kB.w
                 + qeB.x*eav.x + qeB.y*eav.y + qeB.z*eav.z + qeB.w*eav.w;
        pA += __shfl_xor_sync(0xffffffffu, pA, 1);
        pA += __shfl_xor_sync(0xffffffffu, pA, 2);
        pB += __shfl_xor_sync(0xffffffffu, pB, 1);
        pB += __shfl_xor_sync(0xffffffffu, pB, 2);
        if (valid) {
            float aA = pA * 0.25f, aB = pB * 0.25f;
            float nmA = fmaxf(mA, aA), nmB = fmaxf(mB, aB);
            float scA = __expf(mA - nmA), scB = __expf(mB - nmB);
            float exA = __expf(aA - nmA), exB = __expf(aB - nmB);
            mA = nmA; mB = nmB;
            dA = dA * scA + exA; dB = dB * scB + exB;
            vaccA.x = vaccA.x * scA + exA * vA.x;
            vaccA.y = vaccA.y * scA + exA * vA.y;
            vaccA.z = vaccA.z * scA + exA * vA.z;
            vaccA.w = vaccA.w * scA + exA * vA.w;
            vaccB.x = vaccB.x * scB + exB * vB.x;
            vaccB.y = vaccB.y * scB + exB * vB.y;
            vaccB.z = vaccB.z * scB + exB * vB.z;
            vaccB.w = vaccB.w * scB + exB * vB.w;
            eaccA.x = eaccA.x * scA + exA * eav.x;
            eaccA.y = eaccA.y * scA + exA * eav.y;
            eaccA.z = eaccA.z * scA + exA * eav.z;
            eaccA.w = eaccA.w * scA + exA * eav.w;
            eaccB.x = eaccB.x * scB + exB * eav.x;
            eaccB.y = eaccB.y * scB + exB * eav.y;
            eaccB.z = eaccB.z * scB + exB * eav.z;
            eaccB.w = eaccB.w * scB + exB * eav.w;
        }
    }

    // merge the 4 edge-slot groups
    merge_grp(mA, dA, vaccA, eaccA, 8);
    merge_grp(mB, dB, vaccB, eaccB, 8);
    merge_grp(mA, dA, vaccA, eaccA, 16);
    merge_grp(mB, dB, vaccB, eaccB, 16);

    if (g == 0) {
        int ch = (u & 3) * 4;
        s_e[wid][hA][ch+0] = eaccA.x; s_e[wid][hA][ch+1] = eaccA.y;
        s_e[wid][hA][ch+2] = eaccA.z; s_e[wid][hA][ch+3] = eaccA.w;
        s_e[wid][hA+2][ch+0] = eaccB.x; s_e[wid][hA+2][ch+1] = eaccB.y;
        s_e[wid][hA+2][ch+2] = eaccB.z; s_e[wid][hA+2][ch+3] = eaccB.w;
        if ((u & 3) == 0) { s_den[wid][hA] = dA; s_den[wid][hA+2] = dB; }
    }
    __syncwarp();

    if (g == 0) {
        float invA = 1.f / (s_den[wid][hA] + 1e-16f);
        float invB = 1.f / (s_den[wid][hA+2] + 1e-16f);
        float4 etA = {0,0,0,0}, etB = {0,0,0,0};
#pragma unroll
        for (int i = 0; i < EIN; i++) {
            float evA = s_e[wid][hA][i];
            float evB = s_e[wid][hA+2][i];
            float4 wA = *(const float4*)&sWe[i * HID + u * 4];
            float4 wB = *(const float4*)&sWe[i * HID + 32 + u * 4];
            etA.x += evA * wA.x; etA.y += evA * wA.y;
            etA.z += evA * wA.z; etA.w += evA * wA.w;
            etB.x += evB * wB.x; etB.y += evB * wB.y;
            etB.z += evB * wB.z; etB.w += evB * wB.w;
        }
        size_t base = (size_t)n * HID;
        float4 skA = *(const float4*)&g_skip[base + u * 4];
        float4 skB = *(const float4*)&g_skip[base + 32 + u * 4];
        float4 hvA = *(float4*)&g_h[base + u * 4];
        float4 hvB = *(float4*)&g_h[base + 32 + u * 4];
        hvA.x += fmaxf((vaccA.x + etA.x) * invA + skA.x, 0.f);
        hvA.y += fmaxf((vaccA.y + etA.y) * invA + skA.y, 0.f);
        hvA.z += fmaxf((vaccA.z + etA.z) * invA + skA.z, 0.f);
        hvA.w += fmaxf((vaccA.w + etA.w) * invA + skA.w, 0.f);
        hvB.x += fmaxf((vaccB.x + etB.x) * invB + skB.x, 0.f);
        hvB.y += fmaxf((vaccB.y + etB.y) * invB + skB.y, 0.f);
        hvB.z += fmaxf((vaccB.z + etB.z) * invB + skB.z, 0.f);
        hvB.w += fmaxf((vaccB.w + etB.w) * invB + skB.w, 0.f);
        *(float4*)&g_h[base + u * 4] = hvA;
        *(float4*)&g_h[base + 32 + u * 4] = hvB;
    }
}

// ---------------- pooling + MLP ---------------------------------------------
__global__ void k_poolzero() {
    int t = threadIdx.x;
    for (int i = t; i < GG * HID; i += 256) g_pool[i] = 0.f;
    if (t < GG) g_cnt[t] = 0.f;
}
__global__ void k_pool(const int* __restrict__ batch) {
    long idx = (long)blockIdx.x * 256 + threadIdx.x;
    int n = (int)(idx >> 4), cg = (int)(idx & 15);
    if (n >= NN) return;
    int b = batch[n];
    float4 hv = *(const float4*)&g_h[n * HID + cg * 4];
    red_add_v4(&g_pool[b * HID + cg * 4], hv);
    if (cg == 0) red_add_f(&g_cnt[b], 1.f);
}
__global__ void k_mlp(const float* __restrict__ W1, const float* __restrict__ b1,
                      const float* __restrict__ W2, const float* __restrict__ b2,
                      float* __restrict__ out) {
    __shared__ float sm[HID];
    int g = blockIdx.x, t = threadIdx.x;
    float cnt = fmaxf(g_cnt[g], 1.f);
    sm[t] = g_pool[g * HID + t] / cnt;
    __syncthreads();
    if (t < 32) {
        float r = b1[t];
#pragma unroll
        for (int i = 0; i < HID; i++) r += sm[i] * W1[i * 32 + t];
        r = fmaxf(r, 0.f) * W2[t];
#pragma unroll
        for (int o = 16; o; o >>= 1) r += __shfl_down_sync(0xffffffffu, r, o);
        if (t == 0) out[g] = r + b2[0];
    }
}

// ---------------- launch ----------------------------------------------------
extern "C" void kernel_launch(void* const* d_in, const int* in_sizes, int n_in,
                              void* d_out, int out_size) {
    const float* x   = (const float*)d_in[0];
    const int*   ei  = (const int*)d_in[1];
    const float* ea  = (const float*)d_in[2];
    const int*   bat = (const int*)d_in[3];
    const float* Wn  = (const float*)d_in[4];
    const float* bn  = (const float*)d_in[5];
    const float* Wq  = (const float*)d_in[6];
    const float* bq  = (const float*)d_in[7];
    const float* Wk  = (const float*)d_in[8];
    const float* bk  = (const float*)d_in[9];
    const float* Wv  = (const float*)d_in[10];
    const float* bv  = (const float*)d_in[11];
    const float* We  = (const float*)d_in[12];
    const float* Ws  = (const float*)d_in[13];
    const float* bs  = (const float*)d_in[14];
    const float* W1  = (const float*)d_in[15];
    const float* b1  = (const float*)d_in[16];
    const float* W2  = (const float*)d_in[17];
    const float* b2  = (const float*)d_in[18];
    float* out = (float*)d_out;

    const int QKVS_SMEM = (4 * 4096 + 256 + 16 * 68 + 1024) * (int)sizeof(float); // 75008
    cudaFuncSetAttribute(k_qkvs, cudaFuncAttributeMaxDynamicSharedMemorySize, QKVS_SMEM);

    const int NODE_BLOCKS = NN / 16;          // 3125 (exact)
    const int SCAN_BLOCKS = (NN + 255) / 256; // 196
    const int EDGE1T      = EE / 256;         // 6250
    const int EDGE4T      = EE * 4 / 256;     // 25000

    // CSR sort (once per launch, reused by all 3 layers)
    k_zerodeg<<<SCAN_BLOCKS, 256>>>();
    k_hist<<<EDGE1T, 256>>>(ei);
    k_scanA<<<SCAN_BLOCKS, 256>>>();
    k_scanB<<<1, 256>>>(SCAN_BLOCKS);
    k_scanC<<<SCAN_BLOCKS, 256>>>();
    k_scatter<<<EDGE4T, 256>>>(ei, ea);

    k_input<<<NODE_BLOCKS, 256>>>(x, Wn, bn);
    for (int l = 0; l < 3; l++) {
        k_qkvs<<<NODE_BLOCKS, 256, QKVS_SMEM>>>(
            Wq + l * HID * HID, bq + l * HID,
            Wk + l * HID * HID, bk + l * HID,
            Wv + l * HID * HID, bv + l * HID,
            Ws + l * HID * HID, bs + l * HID,
            We + l * EIN * HID);
        k_edge<<<NN / 8, 256>>>(We + l * EIN * HID);
    }
    k_poolzero<<<1, 256>>>();
    k_pool<<<NODE_BLOCKS, 256>>>(bat);
    k_mlp<<<GG, 64>>>(W1, b1, W2, b2, out);
}

// round 10
// speedup vs baseline: 2.7560x; 1.1102x over previous
#include <cuda_runtime.h>
#include <cuda_fp16.h>
#include <math.h>

#define NN 50000
#define EE 1600000
#define GG 64
#define HID 64
#define NH 4
#define CH 16
#define NIN 32
#define EIN 16

// ---------------- scratch (device globals; no allocation allowed) ----------
__device__ __align__(16) float  g_h[NN * HID];
__device__ __align__(16) float  g_q[NN * HID];
__device__ __align__(16) float  g_skip[NN * HID];
__device__ __align__(16) float  g_qe[NN * HID];
__device__ __align__(16) __half g_kvh[(size_t)NN * 128];    // per node: k[64] then v[64], fp16
__device__ __align__(16) __half g_eash[(size_t)EE * EIN];   // ea, dst-sorted, fp16
__device__ int   g_src[EE];
__device__ int   g_deg[NN];
__device__ int   g_off[NN + 1];
__device__ int   g_ctr[NN];
__device__ int   g_part[256];
__device__ int   g_partpre[256];
__device__ __align__(16) float g_pool[GG * HID];
__device__ float g_cnt[GG];

__device__ __forceinline__ void red_add_v4(float* p, float4 v) {
    asm volatile("red.global.add.v4.f32 [%0], {%1,%2,%3,%4};"
                 :: "l"(p), "f"(v.x), "f"(v.y), "f"(v.z), "f"(v.w) : "memory");
}
__device__ __forceinline__ void red_add_f(float* p, float v) {
    asm volatile("red.global.add.f32 [%0], %1;" :: "l"(p), "f"(v) : "memory");
}
__device__ __forceinline__ void fma2(unsigned long long& d,
                                     unsigned long long a, unsigned long long b) {
    asm("fma.rn.f32x2 %0, %1, %2, %0;" : "+l"(d) : "l"(a), "l"(b));
}
__device__ __forceinline__ unsigned long long pack2(float lo, float hi) {
    unsigned long long r;
    asm("mov.b64 %0, {%1, %2};" : "=l"(r) : "f"(lo), "f"(hi));
    return r;
}
__device__ __forceinline__ float unpack_sum(unsigned long long v) {
    float lo, hi;
    asm("mov.b64 {%0, %1}, %2;" : "=f"(lo), "=f"(hi) : "l"(v));
    return lo + hi;
}

// ---------------- input layer: h = relu(x @ Wn + bn) ------------------------
__global__ void k_input(const float* __restrict__ x,
                        const float* __restrict__ Wn,
                        const float* __restrict__ bn) {
    __shared__ float sW[NIN * HID];
    __shared__ float sx[16][NIN + 2];
    __shared__ float sb[HID];
    int t = threadIdx.x;
    for (int i = t; i < NIN * HID; i += 256) sW[i] = Wn[i];
    if (t < HID) sb[t] = bn[t];
    int nb = blockIdx.x * 16;
    for (int i = t; i < 16 * NIN; i += 256) {
        int r = i / NIN, c = i % NIN;
        sx[r][c] = x[(nb + r) * NIN + c];
    }
    __syncthreads();
    int cw = t & 15;
    int r  = t >> 4;
    int n  = nb + r;
    float a0 = sb[cw*4], a1 = sb[cw*4+1], a2 = sb[cw*4+2], a3 = sb[cw*4+3];
#pragma unroll
    for (int i = 0; i < NIN; i++) {
        float hv = sx[r][i];
        float4 w = *(const float4*)&sW[i * HID + cw * 4];
        a0 += hv * w.x; a1 += hv * w.y; a2 += hv * w.z; a3 += hv * w.w;
    }
    float4 o = make_float4(fmaxf(a0,0.f), fmaxf(a1,0.f), fmaxf(a2,0.f), fmaxf(a3,0.f));
    *(float4*)&g_h[n * HID + cw * 4] = o;
}

// ---------------- CSR sort by dst -------------------------------------------
__global__ void k_zerodeg() {
    int i = blockIdx.x * 256 + threadIdx.x;
    if (i < NN) g_deg[i] = 0;
}
__global__ void k_hist(const int* __restrict__ ei) {
    int e = blockIdx.x * 256 + threadIdx.x;
    atomicAdd(&g_deg[ei[EE + e]], 1);
}
__global__ void k_scanA() {
    __shared__ int sp[256];
    int t = threadIdx.x, i = blockIdx.x * 256 + t;
    int d = (i < NN) ? g_deg[i] : 0;
    sp[t] = d; __syncthreads();
    for (int off = 128; off; off >>= 1) {
        if (t < off) sp[t] += sp[t + off];
        __syncthreads();
    }
    if (t == 0) g_part[blockIdx.x] = sp[0];
}
__global__ void k_scanB(int nparts) {
    __shared__ int sp[256];
    int t = threadIdx.x;
    int v = (t < nparts) ? g_part[t] : 0;
    sp[t] = v; __syncthreads();
    for (int off = 1; off < 256; off <<= 1) {
        int u = (t >= off) ? sp[t - off] : 0;
        __syncthreads();
        sp[t] += u;
        __syncthreads();
    }
    g_partpre[t] = sp[t] - v;   // exclusive
}
__global__ void k_scanC() {
    __shared__ int sp[256];
    int t = threadIdx.x, b = blockIdx.x, i = b * 256 + t;
    int d = (i < NN) ? g_deg[i] : 0;
    sp[t] = d; __syncthreads();
    for (int off = 1; off < 256; off <<= 1) {
        int u = (t >= off) ? sp[t - off] : 0;
        __syncthreads();
        sp[t] += u;
        __syncthreads();
    }
    int off0 = g_partpre[b] + sp[t] - d;   // exclusive
    if (i < NN) { g_off[i] = off0; g_ctr[i] = off0; }
    if (b == 0 && t == 0) g_off[NN] = EE;
}
__global__ void k_scatter(const int* __restrict__ ei, const float* __restrict__ ea) {
    long tid = (long)blockIdx.x * 256 + threadIdx.x;
    long e = tid >> 2;
    int  j = (int)(tid & 3);
    int lane = threadIdx.x & 31;
    int pos = 0;
    if (j == 0) {
        int d = ei[EE + e];
        pos = atomicAdd(&g_ctr[d], 1);
        g_src[pos] = ei[e];
    }
    pos = __shfl_sync(0xffffffffu, pos, lane & ~3);
    float4 v = ((const float4*)&ea[(size_t)e * EIN])[j];
    __half2 p0 = __float22half2_rn(make_float2(v.x, v.y));
    __half2 p1 = __float22half2_rn(make_float2(v.z, v.w));
    size_t base = (size_t)pos * EIN + j * 4;
    *(__half2*)&g_eash[base]     = p0;
    *(__half2*)&g_eash[base + 2] = p1;
}

// ---------------- per-layer node linears: q,k,v,skip + qe (fused) -----------
// dyn smem: sW2[4*4096] (i-interleaved pairs) + sb[256] + sh[16*68] + sWe[1024]
__global__ void k_qkvs(const float* __restrict__ Wq, const float* __restrict__ bq,
                       const float* __restrict__ Wk, const float* __restrict__ bk,
                       const float* __restrict__ Wv, const float* __restrict__ bv,
                       const float* __restrict__ Ws, const float* __restrict__ bs,
                       const float* __restrict__ We) {
    extern __shared__ float sm[];
    float* sW2 = sm;                    // 16384 (also aliased as sq later)
    float* sb  = sm + 16384;            // 256
    float* sh  = sm + 16640;            // 16*68
    float* sWe = sm + 17728;            // 1024
    int t = threadIdx.x;
    const float* Wp[4] = {Wq, Wk, Wv, Ws};
    const float* bp[4] = {bq, bk, bv, bs};
#pragma unroll
    for (int a0 = 0; a0 < 4; a0++)
        for (int idx = t; idx < 4096; idx += 256) {
            int i = idx >> 6, c = idx & 63;
            sW2[a0 * 4096 + ((i >> 1) << 7) + (c << 1) + (i & 1)] = Wp[a0][idx];
        }
    sb[t] = bp[t >> 6][t & 63];
    for (int i = t; i < 1024; i += 256) sWe[i] = We[i];
    int nb = blockIdx.x * 16;
    for (int i = t; i < 16 * HID; i += 256) {
        int r = i >> 6, c = i & 63;
        sh[r * 68 + c] = g_h[(nb + r) * HID + c];
    }
    __syncthreads();

    int a  = t >> 6;          // array: 0=q 1=k 2=v 3=skip
    int cw = t & 15;          // 4-col group
    int nq = (t >> 4) & 3;    // 4-node group
    unsigned long long acc2[4][4];
#pragma unroll
    for (int m = 0; m < 4; m++)
#pragma unroll
        for (int c = 0; c < 4; c++)
            acc2[m][c] = pack2(sb[a * 64 + cw * 4 + c], 0.f);
    const float* wbase = &sW2[a * 4096 + cw * 8];
#pragma unroll 4
    for (int i2 = 0; i2 < 32; i2++) {
        ulonglong2 w01 = *(const ulonglong2*)&wbase[i2 * 128];
        ulonglong2 w23 = *(const ulonglong2*)&wbase[i2 * 128 + 4];
#pragma unroll
        for (int m = 0; m < 4; m++) {
            unsigned long long hv =
                *(const unsigned long long*)&sh[(nq * 4 + m) * 68 + i2 * 2];
            fma2(acc2[m][0], hv, w01.x);
            fma2(acc2[m][1], hv, w01.y);
            fma2(acc2[m][2], hv, w23.x);
            fma2(acc2[m][3], hv, w23.y);
        }
    }
    float o[4][4];
#pragma unroll
    for (int m = 0; m < 4; m++)
#pragma unroll
        for (int c = 0; c < 4; c++) o[m][c] = unpack_sum(acc2[m][c]);

    if (a == 1 || a == 2) {
        // k or v -> fp16 interleaved g_kvh (k at 0, v at 64)
        int voff = (a == 2) ? 64 : 0;
#pragma unroll
        for (int m = 0; m < 4; m++) {
            __half2 p0 = __float22half2_rn(make_float2(o[m][0], o[m][1]));
            __half2 p1 = __float22half2_rn(make_float2(o[m][2], o[m][3]));
            __half2* dst = (__half2*)&g_kvh[(size_t)(nb + nq * 4 + m) * 128 + voff + cw * 4];
            dst[0] = p0; dst[1] = p1;
        }
    } else {
        float* outp = (a == 0) ? g_q : g_skip;
#pragma unroll
        for (int m = 0; m < 4; m++)
            *(float4*)&outp[(nb + nq * 4 + m) * HID + cw * 4] =
                make_float4(o[m][0], o[m][1], o[m][2], o[m][3]);
    }
    __syncthreads();
    // stage q into sq (alias sW2[0..1024)) for qe
    float* sq = sm;
    if (a == 0)
#pragma unroll
        for (int m = 0; m < 4; m++)
#pragma unroll
            for (int c = 0; c < 4; c++)
                sq[(nq * 4 + m) * 64 + cw * 4 + c] = o[m][c];
    __syncthreads();
    // qe[n, h*16+i0] = sum_c We[i0, h*16+c] * q[n, h*16+c]
#pragma unroll
    for (int kk = 0; kk < 4; kk++) {
        int oo = t + 256 * kk;
        int r = oo >> 6, j = oo & 63, h = j >> 4, i0 = j & 15;
        float s = 0.f;
#pragma unroll
        for (int c = 0; c < CH; c++)
            s += sWe[i0 * HID + h * CH + c] * sq[r * 64 + h * CH + c];
        g_qe[(nb + r) * HID + j] = s;
    }
}

// ---------------- fused edge pass: online softmax + aggregate + update ------
// warp per dst node; 4 edge-slots (g) x 8 lanes (u). Lane u owns cols
// c0=8u..8u+7, i.e. head h=u>>1, ea-half = u&1. One exp set per lane.
__global__ void __launch_bounds__(256, 3) k_edge(const float* __restrict__ We) {
    __shared__ float sWe[EIN * HID];
    __shared__ float s_e[8][4][16];
    __shared__ float s_den[8][4];
    int t = threadIdx.x;
    for (int i = t; i < EIN * HID; i += 256) sWe[i] = We[i];
    __syncthreads();
    int wid = t >> 5, lane = t & 31;
    int n = blockIdx.x * 8 + wid;      // grid = 6250, exact
    int g = lane >> 3, u = lane & 7;
    int h = u >> 1, half = u & 1;
    int c0 = u * 8;                    // owned column range
    int begin = g_off[n], end = g_off[n + 1];
    int nIter = (end - begin + 3) >> 2;   // warp-uniform

    float q[8], qe[8];
    {
        const float4* qp  = (const float4*)&g_q [(size_t)n * HID + c0];
        const float4* qep = (const float4*)&g_qe[(size_t)n * HID + c0];
        float4 a0 = qp[0], a1 = qp[1], b0 = qep[0], b1 = qep[1];
        q[0]=a0.x; q[1]=a0.y; q[2]=a0.z; q[3]=a0.w;
        q[4]=a1.x; q[5]=a1.y; q[6]=a1.z; q[7]=a1.w;
        qe[0]=b0.x; qe[1]=b0.y; qe[2]=b0.z; qe[3]=b0.w;
        qe[4]=b1.x; qe[5]=b1.y; qe[6]=b1.z; qe[7]=b1.w;
    }

    float m = -1e30f, den = 0.f;
    float vacc[8] = {}, eacc[8] = {};

    if (nIter > 0) {
        int pc = min(begin + g, end - 1);
        int s = g_src[pc];
        uint4 eaq = __ldcs((const uint4*)&g_eash[(size_t)pc * EIN + half * 8]);
        for (int it = 0; it < nIter; it++) {
            // current kv loads (s resident from prefetch)
            const uint4* kvp = (const uint4*)&g_kvh[(size_t)s * 128];
            uint4 kh = kvp[u];
            uint4 vh = kvp[8 + u];
            int pos = begin + it * 4 + g;
            bool valid = pos < end;
            // prefetch next src + ea (warp-uniform branch)
            int s_n = s; uint4 ea_n = eaq;
            if (it + 1 < nIter) {
                int pc_n = min(begin + (it + 1) * 4 + g, end - 1);
                s_n = g_src[pc_n];
                ea_n = __ldcs((const uint4*)&g_eash[(size_t)pc_n * EIN + half * 8]);
            }
            // convert fp16 -> fp32
            float kf[8], vf[8], eaf[8];
            {
                __half2* kp2 = (__half2*)&kh;
                __half2* vp2 = (__half2*)&vh;
                __half2* ep2 = (__half2*)&eaq;
#pragma unroll
                for (int i = 0; i < 4; i++) {
                    float2 kk = __half22float2(kp2[i]);
                    float2 vv = __half22float2(vp2[i]);
                    float2 ee = __half22float2(ep2[i]);
                    kf[i*2] = kk.x; kf[i*2+1] = kk.y;
                    vf[i*2] = vv.x; vf[i*2+1] = vv.y;
                    eaf[i*2] = ee.x; eaf[i*2+1] = ee.y;
                }
            }
            float p = 0.f;
#pragma unroll
            for (int i = 0; i < 8; i++) p += q[i] * kf[i] + qe[i] * eaf[i];
            p += __shfl_xor_sync(0xffffffffu, p, 1);   // combine head halves
            if (valid) {
                float alpha = p * 0.25f;
                float nm = fmaxf(m, alpha);
                float sc = __expf(m - nm);
                float ex = __expf(alpha - nm);
                m = nm;
                den = den * sc + ex;
#pragma unroll
                for (int i = 0; i < 8; i++) {
                    vacc[i] = vacc[i] * sc + ex * vf[i];
                    eacc[i] = eacc[i] * sc + ex * eaf[i];
                }
            }
            s = s_n; eaq = ea_n;
        }
    }

    // merge the 4 edge-slot groups (online-softmax merge)
#pragma unroll
    for (int off = 8; off <= 16; off <<= 1) {
        float m2 = __shfl_xor_sync(0xffffffffu, m, off);
        float d2 = __shfl_xor_sync(0xffffffffu, den, off);
        float nm = fmaxf(m, m2);
        float s1 = __expf(m - nm), s2 = __expf(m2 - nm);
        den = den * s1 + d2 * s2;
#pragma unroll
        for (int i = 0; i < 8; i++) {
            float v2 = __shfl_xor_sync(0xffffffffu, vacc[i], off);
            vacc[i] = vacc[i] * s1 + v2 * s2;
            float e2 = __shfl_xor_sync(0xffffffffu, eacc[i], off);
            eacc[i] = eacc[i] * s1 + e2 * s2;
        }
        m = nm;
    }

    if (g == 0) {
#pragma unroll
        for (int i = 0; i < 8; i++) s_e[wid][h][half * 8 + i] = eacc[i];
        if (half == 0) s_den[wid][h] = den;
    }
    __syncwarp();

    if (g == 0) {
        float inv = 1.f / (s_den[wid][h] + 1e-16f);
        float et[8] = {};
#pragma unroll
        for (int j = 0; j < EIN; j++) {
            float ev = s_e[wid][h][j];
            float4 w0 = *(const float4*)&sWe[j * HID + c0];
            float4 w1 = *(const float4*)&sWe[j * HID + c0 + 4];
            et[0] += ev * w0.x; et[1] += ev * w0.y;
            et[2] += ev * w0.z; et[3] += ev * w0.w;
            et[4] += ev * w1.x; et[5] += ev * w1.y;
            et[6] += ev * w1.z; et[7] += ev * w1.w;
        }
        size_t base = (size_t)n * HID + c0;
        float4 sk0 = *(const float4*)&g_skip[base];
        float4 sk1 = *(const float4*)&g_skip[base + 4];
        float4 hv0 = *(float4*)&g_h[base];
        float4 hv1 = *(float4*)&g_h[base + 4];
        hv0.x += fmaxf((vacc[0] + et[0]) * inv + sk0.x, 0.f);
        hv0.y += fmaxf((vacc[1] + et[1]) * inv + sk0.y, 0.f);
        hv0.z += fmaxf((vacc[2] + et[2]) * inv + sk0.z, 0.f);
        hv0.w += fmaxf((vacc[3] + et[3]) * inv + sk0.w, 0.f);
        hv1.x += fmaxf((vacc[4] + et[4]) * inv + sk1.x, 0.f);
        hv1.y += fmaxf((vacc[5] + et[5]) * inv + sk1.y, 0.f);
        hv1.z += fmaxf((vacc[6] + et[6]) * inv + sk1.z, 0.f);
        hv1.w += fmaxf((vacc[7] + et[7]) * inv + sk1.w, 0.f);
        *(float4*)&g_h[base] = hv0;
        *(float4*)&g_h[base + 4] = hv1;
    }
}

// ---------------- pooling + MLP ---------------------------------------------
__global__ void k_poolzero() {
    int t = threadIdx.x;
    for (int i = t; i < GG * HID; i += 256) g_pool[i] = 0.f;
    if (t < GG) g_cnt[t] = 0.f;
}
__global__ void k_pool(const int* __restrict__ batch) {
    long idx = (long)blockIdx.x * 256 + threadIdx.x;
    int n = (int)(idx >> 4), cg = (int)(idx & 15);
    if (n >= NN) return;
    int b = batch[n];
    float4 hv = *(const float4*)&g_h[n * HID + cg * 4];
    red_add_v4(&g_pool[b * HID + cg * 4], hv);
    if (cg == 0) red_add_f(&g_cnt[b], 1.f);
}
__global__ void k_mlp(const float* __restrict__ W1, const float* __restrict__ b1,
                      const float* __restrict__ W2, const float* __restrict__ b2,
                      float* __restrict__ out) {
    __shared__ float sm[HID];
    int g = blockIdx.x, t = threadIdx.x;
    float cnt = fmaxf(g_cnt[g], 1.f);
    sm[t] = g_pool[g * HID + t] / cnt;
    __syncthreads();
    if (t < 32) {
        float r = b1[t];
#pragma unroll
        for (int i = 0; i < HID; i++) r += sm[i] * W1[i * 32 + t];
        r = fmaxf(r, 0.f) * W2[t];
#pragma unroll
        for (int o = 16; o; o >>= 1) r += __shfl_down_sync(0xffffffffu, r, o);
        if (t == 0) out[g] = r + b2[0];
    }
}

// ---------------- launch ----------------------------------------------------
extern "C" void kernel_launch(void* const* d_in, const int* in_sizes, int n_in,
                              void* d_out, int out_size) {
    const float* x   = (const float*)d_in[0];
    const int*   ei  = (const int*)d_in[1];
    const float* ea  = (const float*)d_in[2];
    const int*   bat = (const int*)d_in[3];
    const float* Wn  = (const float*)d_in[4];
    const float* bn  = (const float*)d_in[5];
    const float* Wq  = (const float*)d_in[6];
    const float* bq  = (const float*)d_in[7];
    const float* Wk  = (const float*)d_in[8];
    const float* bk  = (const float*)d_in[9];
    const float* Wv  = (const float*)d_in[10];
    const float* bv  = (const float*)d_in[11];
    const float* We  = (const float*)d_in[12];
    const float* Ws  = (const float*)d_in[13];
    const float* bs  = (const float*)d_in[14];
    const float* W1  = (const float*)d_in[15];
    const float* b1  = (const float*)d_in[16];
    const float* W2  = (const float*)d_in[17];
    const float* b2  = (const float*)d_in[18];
    float* out = (float*)d_out;

    const int QKVS_SMEM = (4 * 4096 + 256 + 16 * 68 + 1024) * (int)sizeof(float); // 75008
    cudaFuncSetAttribute(k_qkvs, cudaFuncAttributeMaxDynamicSharedMemorySize, QKVS_SMEM);

    const int NODE_BLOCKS = NN / 16;          // 3125 (exact)
    const int SCAN_BLOCKS = (NN + 255) / 256; // 196
    const int EDGE1T      = EE / 256;         // 6250
    const int EDGE4T      = EE * 4 / 256;     // 25000

    // CSR sort (once per launch, reused by all 3 layers)
    k_zerodeg<<<SCAN_BLOCKS, 256>>>();
    k_hist<<<EDGE1T, 256>>>(ei);
    k_scanA<<<SCAN_BLOCKS, 256>>>();
    k_scanB<<<1, 256>>>(SCAN_BLOCKS);
    k_scanC<<<SCAN_BLOCKS, 256>>>();
    k_scatter<<<EDGE4T, 256>>>(ei, ea);

    k_input<<<NODE_BLOCKS, 256>>>(x, Wn, bn);
    for (int l = 0; l < 3; l++) {
        k_qkvs<<<NODE_BLOCKS, 256, QKVS_SMEM>>>(
            Wq + l * HID * HID, bq + l * HID,
            Wk + l * HID * HID, bk + l * HID,
            Wv + l * HID * HID, bv + l * HID,
            Ws + l * HID * HID, bs + l * HID,
            We + l * EIN * HID);
        k_edge<<<NN / 8, 256>>>(We + l * EIN * HID);
    }
    k_poolzero<<<1, 256>>>();
    k_pool<<<NODE_BLOCKS, 256>>>(bat);
    k_mlp<<<GG, 64>>>(W1, b1, W2, b2, out);
}

// round 11
// speedup vs baseline: 2.7814x; 1.0092x over previous
#include <cuda_runtime.h>
#include <cuda_fp16.h>
#include <math.h>

#define NN 50000
#define EE 1600000
#define GG 64
#define HID 64
#define NH 4
#define CH 16
#define NIN 32
#define EIN 16

// ---------------- scratch (device globals; no allocation allowed) ----------
__device__ __align__(16) float  g_h[NN * HID];
__device__ __align__(16) float  g_q[NN * HID];
__device__ __align__(16) float  g_skip[NN * HID];
__device__ __align__(16) float  g_qe[NN * HID];
__device__ __align__(16) __half g_kvh[(size_t)NN * 128];    // per node: k[64] then v[64], fp16
__device__ __align__(16) __half g_eash[(size_t)EE * EIN];   // ea, dst-sorted, fp16
__device__ int   g_src[EE];
__device__ int   g_deg[NN];
__device__ int   g_off[NN + 1];
__device__ int   g_ctr[NN];
__device__ int   g_part[256];
__device__ int   g_partpre[256];
__device__ __align__(16) float g_pool[GG * HID];
__device__ float g_cnt[GG];

__device__ __forceinline__ void red_add_v4(float* p, float4 v) {
    asm volatile("red.global.add.v4.f32 [%0], {%1,%2,%3,%4};"
                 :: "l"(p), "f"(v.x), "f"(v.y), "f"(v.z), "f"(v.w) : "memory");
}
__device__ __forceinline__ void red_add_f(float* p, float v) {
    asm volatile("red.global.add.f32 [%0], %1;" :: "l"(p), "f"(v) : "memory");
}
__device__ __forceinline__ void fma2(unsigned long long& d,
                                     unsigned long long a, unsigned long long b) {
    asm("fma.rn.f32x2 %0, %1, %2, %0;" : "+l"(d) : "l"(a), "l"(b));
}
__device__ __forceinline__ unsigned long long pack2(float lo, float hi) {
    unsigned long long r;
    asm("mov.b64 %0, {%1, %2};" : "=l"(r) : "f"(lo), "f"(hi));
    return r;
}
__device__ __forceinline__ float unpack_sum(unsigned long long v) {
    float lo, hi;
    asm("mov.b64 {%0, %1}, %2;" : "=f"(lo), "=f"(hi) : "l"(v));
    return lo + hi;
}

// ---------------- input layer: h = relu(x @ Wn + bn) ------------------------
__global__ void k_input(const float* __restrict__ x,
                        const float* __restrict__ Wn,
                        const float* __restrict__ bn) {
    __shared__ float sW[NIN * HID];
    __shared__ float sx[16][NIN + 2];
    __shared__ float sb[HID];
    int t = threadIdx.x;
    for (int i = t; i < NIN * HID; i += 256) sW[i] = Wn[i];
    if (t < HID) sb[t] = bn[t];
    int nb = blockIdx.x * 16;
    for (int i = t; i < 16 * NIN; i += 256) {
        int r = i / NIN, c = i % NIN;
        sx[r][c] = x[(nb + r) * NIN + c];
    }
    __syncthreads();
    int cw = t & 15;
    int r  = t >> 4;
    int n  = nb + r;
    float a0 = sb[cw*4], a1 = sb[cw*4+1], a2 = sb[cw*4+2], a3 = sb[cw*4+3];
#pragma unroll
    for (int i = 0; i < NIN; i++) {
        float hv = sx[r][i];
        float4 w = *(const float4*)&sW[i * HID + cw * 4];
        a0 += hv * w.x; a1 += hv * w.y; a2 += hv * w.z; a3 += hv * w.w;
    }
    float4 o = make_float4(fmaxf(a0,0.f), fmaxf(a1,0.f), fmaxf(a2,0.f), fmaxf(a3,0.f));
    *(float4*)&g_h[n * HID + cw * 4] = o;
}

// ---------------- CSR sort by dst -------------------------------------------
__global__ void k_zerodeg() {
    int i = blockIdx.x * 256 + threadIdx.x;
    if (i < NN) g_deg[i] = 0;
}
__global__ void k_hist(const int* __restrict__ ei) {
    int e = blockIdx.x * 256 + threadIdx.x;
    atomicAdd(&g_deg[ei[EE + e]], 1);
}
__global__ void k_scanA() {
    __shared__ int sp[256];
    int t = threadIdx.x, i = blockIdx.x * 256 + t;
    int d = (i < NN) ? g_deg[i] : 0;
    sp[t] = d; __syncthreads();
    for (int off = 128; off; off >>= 1) {
        if (t < off) sp[t] += sp[t + off];
        __syncthreads();
    }
    if (t == 0) g_part[blockIdx.x] = sp[0];
}
__global__ void k_scanB(int nparts) {
    __shared__ int sp[256];
    int t = threadIdx.x;
    int v = (t < nparts) ? g_part[t] : 0;
    sp[t] = v; __syncthreads();
    for (int off = 1; off < 256; off <<= 1) {
        int u = (t >= off) ? sp[t - off] : 0;
        __syncthreads();
        sp[t] += u;
        __syncthreads();
    }
    g_partpre[t] = sp[t] - v;   // exclusive
}
__global__ void k_scanC() {
    __shared__ int sp[256];
    int t = threadIdx.x, b = blockIdx.x, i = b * 256 + t;
    int d = (i < NN) ? g_deg[i] : 0;
    sp[t] = d; __syncthreads();
    for (int off = 1; off < 256; off <<= 1) {
        int u = (t >= off) ? sp[t - off] : 0;
        __syncthreads();
        sp[t] += u;
        __syncthreads();
    }
    int off0 = g_partpre[b] + sp[t] - d;   // exclusive
    if (i < NN) { g_off[i] = off0; g_ctr[i] = off0; }
    if (b == 0 && t == 0) g_off[NN] = EE;
}
__global__ void k_scatter(const int* __restrict__ ei, const float* __restrict__ ea) {
    long tid = (long)blockIdx.x * 256 + threadIdx.x;
    long e = tid >> 2;
    int  j = (int)(tid & 3);
    int lane = threadIdx.x & 31;
    int pos = 0;
    if (j == 0) {
        int d = ei[EE + e];
        pos = atomicAdd(&g_ctr[d], 1);
        g_src[pos] = ei[e];
    }
    pos = __shfl_sync(0xffffffffu, pos, lane & ~3);
    float4 v = ((const float4*)&ea[(size_t)e * EIN])[j];
    __half2 p0 = __float22half2_rn(make_float2(v.x, v.y));
    __half2 p1 = __float22half2_rn(make_float2(v.z, v.w));
    size_t base = (size_t)pos * EIN + j * 4;
    *(__half2*)&g_eash[base]     = p0;
    *(__half2*)&g_eash[base + 2] = p1;
}

// ---------------- per-layer node linears: q,k,v,skip + qe (fused) -----------
// dyn smem: sW2[4*4096] (i-interleaved pairs) + sb[256] + sh[16*68] + sWe[1024]
__global__ void k_qkvs(const float* __restrict__ Wq, const float* __restrict__ bq,
                       const float* __restrict__ Wk, const float* __restrict__ bk,
                       const float* __restrict__ Wv, const float* __restrict__ bv,
                       const float* __restrict__ Ws, const float* __restrict__ bs,
                       const float* __restrict__ We) {
    extern __shared__ float sm[];
    float* sW2 = sm;                    // 16384 (also aliased as sq later)
    float* sb  = sm + 16384;            // 256
    float* sh  = sm + 16640;            // 16*68
    float* sWe = sm + 17728;            // 1024
    int t = threadIdx.x;
    const float* Wp[4] = {Wq, Wk, Wv, Ws};
    const float* bp[4] = {bq, bk, bv, bs};
#pragma unroll
    for (int a0 = 0; a0 < 4; a0++)
        for (int idx = t; idx < 4096; idx += 256) {
            int i = idx >> 6, c = idx & 63;
            sW2[a0 * 4096 + ((i >> 1) << 7) + (c << 1) + (i & 1)] = Wp[a0][idx];
        }
    sb[t] = bp[t >> 6][t & 63];
    for (int i = t; i < 1024; i += 256) sWe[i] = We[i];
    int nb = blockIdx.x * 16;
    for (int i = t; i < 16 * HID; i += 256) {
        int r = i >> 6, c = i & 63;
        sh[r * 68 + c] = g_h[(nb + r) * HID + c];
    }
    __syncthreads();

    int a  = t >> 6;          // array: 0=q 1=k 2=v 3=skip
    int cw = t & 15;          // 4-col group
    int nq = (t >> 4) & 3;    // 4-node group
    unsigned long long acc2[4][4];
#pragma unroll
    for (int m = 0; m < 4; m++)
#pragma unroll
        for (int c = 0; c < 4; c++)
            acc2[m][c] = pack2(sb[a * 64 + cw * 4 + c], 0.f);
    const float* wbase = &sW2[a * 4096 + cw * 8];
#pragma unroll 4
    for (int i2 = 0; i2 < 32; i2++) {
        ulonglong2 w01 = *(const ulonglong2*)&wbase[i2 * 128];
        ulonglong2 w23 = *(const ulonglong2*)&wbase[i2 * 128 + 4];
#pragma unroll
        for (int m = 0; m < 4; m++) {
            unsigned long long hv =
                *(const unsigned long long*)&sh[(nq * 4 + m) * 68 + i2 * 2];
            fma2(acc2[m][0], hv, w01.x);
            fma2(acc2[m][1], hv, w01.y);
            fma2(acc2[m][2], hv, w23.x);
            fma2(acc2[m][3], hv, w23.y);
        }
    }
    float o[4][4];
#pragma unroll
    for (int m = 0; m < 4; m++)
#pragma unroll
        for (int c = 0; c < 4; c++) o[m][c] = unpack_sum(acc2[m][c]);

    if (a == 1 || a == 2) {
        // k or v -> fp16 interleaved g_kvh (k at 0, v at 64)
        int voff = (a == 2) ? 64 : 0;
#pragma unroll
        for (int m = 0; m < 4; m++) {
            __half2 p0 = __float22half2_rn(make_float2(o[m][0], o[m][1]));
            __half2 p1 = __float22half2_rn(make_float2(o[m][2], o[m][3]));
            __half2* dst = (__half2*)&g_kvh[(size_t)(nb + nq * 4 + m) * 128 + voff + cw * 4];
            dst[0] = p0; dst[1] = p1;
        }
    } else {
        float* outp = (a == 0) ? g_q : g_skip;
#pragma unroll
        for (int m = 0; m < 4; m++)
            *(float4*)&outp[(nb + nq * 4 + m) * HID + cw * 4] =
                make_float4(o[m][0], o[m][1], o[m][2], o[m][3]);
    }
    __syncthreads();
    // stage q into sq (alias sW2[0..1024)) for qe
    float* sq = sm;
    if (a == 0)
#pragma unroll
        for (int m = 0; m < 4; m++)
#pragma unroll
            for (int c = 0; c < 4; c++)
                sq[(nq * 4 + m) * 64 + cw * 4 + c] = o[m][c];
    __syncthreads();
    // qe[n, h*16+i0] = sum_c We[i0, h*16+c] * q[n, h*16+c]
#pragma unroll
    for (int kk = 0; kk < 4; kk++) {
        int oo = t + 256 * kk;
        int r = oo >> 6, j = oo & 63, h = j >> 4, i0 = j & 15;
        float s = 0.f;
#pragma unroll
        for (int c = 0; c < CH; c++)
            s += sWe[i0 * HID + h * CH + c] * sq[r * 64 + h * CH + c];
        g_qe[(nb + r) * HID + j] = s;
    }
}

// ---------------- fused edge pass: online softmax + aggregate + update ------
// warp per dst node; 4 edge-slots (g) x 8 lanes (u). Lane u owns cols
// c0=8u..8u+7, i.e. head h=u>>1, ea-half = u&1.
// 2-deep software pipeline: src/ea prefetched 2 iters ahead, kv 1 iter ahead,
// so the src->kv 2-hop L2 latency chain is off the critical path.
__global__ void __launch_bounds__(256, 3) k_edge(const float* __restrict__ We) {
    __shared__ float sWe[EIN * HID];
    __shared__ float s_e[8][4][16];
    __shared__ float s_den[8][4];
    int t = threadIdx.x;
    for (int i = t; i < EIN * HID; i += 256) sWe[i] = We[i];
    __syncthreads();
    int wid = t >> 5, lane = t & 31;
    int n = blockIdx.x * 8 + wid;      // grid = 6250, exact
    int g = lane >> 3, u = lane & 7;
    int h = u >> 1, half = u & 1;
    int c0 = u * 8;                    // owned column range
    int begin = g_off[n], end = g_off[n + 1];
    int nIter = (end - begin + 3) >> 2;   // warp-uniform

    float q[8], qe[8];
    {
        const float4* qp  = (const float4*)&g_q [(size_t)n * HID + c0];
        const float4* qep = (const float4*)&g_qe[(size_t)n * HID + c0];
        float4 a0 = qp[0], a1 = qp[1], b0 = qep[0], b1 = qep[1];
        q[0]=a0.x; q[1]=a0.y; q[2]=a0.z; q[3]=a0.w;
        q[4]=a1.x; q[5]=a1.y; q[6]=a1.z; q[7]=a1.w;
        qe[0]=b0.x; qe[1]=b0.y; qe[2]=b0.z; qe[3]=b0.w;
        qe[4]=b1.x; qe[5]=b1.y; qe[6]=b1.z; qe[7]=b1.w;
    }

    float m = -1e30f, den = 0.f;
    float vacc[8] = {}, eacc[8] = {};

    if (nIter > 0) {
        // stage 0: src/ea for iter 0, then kv for iter 0 (exposed once)
        int pc0 = min(begin + g, end - 1);
        int s0 = g_src[pc0];
        uint4 eaq = __ldcs((const uint4*)&g_eash[(size_t)pc0 * EIN + half * 8]);
        const uint4* kvp0 = (const uint4*)&g_kvh[(size_t)s0 * 128];
        uint4 kh = kvp0[u];
        uint4 vh = kvp0[8 + u];
        // src/ea for iter 1
        int s1 = s0; uint4 ea1 = eaq;
        if (nIter > 1) {
            int pc1 = min(begin + 4 + g, end - 1);
            s1 = g_src[pc1];
            ea1 = __ldcs((const uint4*)&g_eash[(size_t)pc1 * EIN + half * 8]);
        }
        for (int it = 0; it < nIter; it++) {
            // issue kv loads for iter it+1 (s1 resident)
            uint4 kh_n = kh, vh_n = vh;
            if (it + 1 < nIter) {
                const uint4* kvp = (const uint4*)&g_kvh[(size_t)s1 * 128];
                kh_n = kvp[u];
                vh_n = kvp[8 + u];
            }
            // prefetch src/ea for iter it+2
            int s2 = s1; uint4 ea2 = ea1;
            if (it + 2 < nIter) {
                int pc2 = min(begin + (it + 2) * 4 + g, end - 1);
                s2 = g_src[pc2];
                ea2 = __ldcs((const uint4*)&g_eash[(size_t)pc2 * EIN + half * 8]);
            }
            int pos = begin + it * 4 + g;
            bool valid = pos < end;
            // convert fp16 -> fp32 (current stage, registers already resident)
            float kf[8], vf[8], eaf[8];
            {
                __half2* kp2 = (__half2*)&kh;
                __half2* vp2 = (__half2*)&vh;
                __half2* ep2 = (__half2*)&eaq;
#pragma unroll
                for (int i = 0; i < 4; i++) {
                    float2 kk = __half22float2(kp2[i]);
                    float2 vv = __half22float2(vp2[i]);
                    float2 ee = __half22float2(ep2[i]);
                    kf[i*2] = kk.x; kf[i*2+1] = kk.y;
                    vf[i*2] = vv.x; vf[i*2+1] = vv.y;
                    eaf[i*2] = ee.x; eaf[i*2+1] = ee.y;
                }
            }
            float p = 0.f;
#pragma unroll
            for (int i = 0; i < 8; i++) p += q[i] * kf[i] + qe[i] * eaf[i];
            p += __shfl_xor_sync(0xffffffffu, p, 1);   // combine head halves
            if (valid) {
                float alpha = p * 0.25f;
                float nm = fmaxf(m, alpha);
                float sc = __expf(m - nm);
                float ex = __expf(alpha - nm);
                m = nm;
                den = den * sc + ex;
#pragma unroll
                for (int i = 0; i < 8; i++) {
                    vacc[i] = vacc[i] * sc + ex * vf[i];
                    eacc[i] = eacc[i] * sc + ex * eaf[i];
                }
            }
            kh = kh_n; vh = vh_n; eaq = ea1;
            s1 = s2; ea1 = ea2;
        }
    }

    // merge the 4 edge-slot groups (online-softmax merge)
#pragma unroll
    for (int off = 8; off <= 16; off <<= 1) {
        float m2 = __shfl_xor_sync(0xffffffffu, m, off);
        float d2 = __shfl_xor_sync(0xffffffffu, den, off);
        float nm = fmaxf(m, m2);
        float s1 = __expf(m - nm), s2 = __expf(m2 - nm);
        den = den * s1 + d2 * s2;
#pragma unroll
        for (int i = 0; i < 8; i++) {
            float v2 = __shfl_xor_sync(0xffffffffu, vacc[i], off);
            vacc[i] = vacc[i] * s1 + v2 * s2;
            float e2 = __shfl_xor_sync(0xffffffffu, eacc[i], off);
            eacc[i] = eacc[i] * s1 + e2 * s2;
        }
        m = nm;
    }

    if (g == 0) {
#pragma unroll
        for (int i = 0; i < 8; i++) s_e[wid][h][half * 8 + i] = eacc[i];
        if (half == 0) s_den[wid][h] = den;
    }
    __syncwarp();

    if (g == 0) {
        float inv = 1.f / (s_den[wid][h] + 1e-16f);
        float et[8] = {};
#pragma unroll
        for (int j = 0; j < EIN; j++) {
            float ev = s_e[wid][h][j];
            float4 w0 = *(const float4*)&sWe[j * HID + c0];
            float4 w1 = *(const float4*)&sWe[j * HID + c0 + 4];
            et[0] += ev * w0.x; et[1] += ev * w0.y;
            et[2] += ev * w0.z; et[3] += ev * w0.w;
            et[4] += ev * w1.x; et[5] += ev * w1.y;
            et[6] += ev * w1.z; et[7] += ev * w1.w;
        }
        size_t base = (size_t)n * HID + c0;
        float4 sk0 = *(const float4*)&g_skip[base];
        float4 sk1 = *(const float4*)&g_skip[base + 4];
        float4 hv0 = *(float4*)&g_h[base];
        float4 hv1 = *(float4*)&g_h[base + 4];
        hv0.x += fmaxf((vacc[0] + et[0]) * inv + sk0.x, 0.f);
        hv0.y += fmaxf((vacc[1] + et[1]) * inv + sk0.y, 0.f);
        hv0.z += fmaxf((vacc[2] + et[2]) * inv + sk0.z, 0.f);
        hv0.w += fmaxf((vacc[3] + et[3]) * inv + sk0.w, 0.f);
        hv1.x += fmaxf((vacc[4] + et[4]) * inv + sk1.x, 0.f);
        hv1.y += fmaxf((vacc[5] + et[5]) * inv + sk1.y, 0.f);
        hv1.z += fmaxf((vacc[6] + et[6]) * inv + sk1.z, 0.f);
        hv1.w += fmaxf((vacc[7] + et[7]) * inv + sk1.w, 0.f);
        *(float4*)&g_h[base] = hv0;
        *(float4*)&g_h[base + 4] = hv1;
    }
}

// ---------------- pooling + MLP ---------------------------------------------
__global__ void k_poolzero() {
    int t = threadIdx.x;
    for (int i = t; i < GG * HID; i += 256) g_pool[i] = 0.f;
    if (t < GG) g_cnt[t] = 0.f;
}
__global__ void k_pool(const int* __restrict__ batch) {
    long idx = (long)blockIdx.x * 256 + threadIdx.x;
    int n = (int)(idx >> 4), cg = (int)(idx & 15);
    if (n >= NN) return;
    int b = batch[n];
    float4 hv = *(const float4*)&g_h[n * HID + cg * 4];
    red_add_v4(&g_pool[b * HID + cg * 4], hv);
    if (cg == 0) red_add_f(&g_cnt[b], 1.f);
}
__global__ void k_mlp(const float* __restrict__ W1, const float* __restrict__ b1,
                      const float* __restrict__ W2, const float* __restrict__ b2,
                      float* __restrict__ out) {
    __shared__ float sm[HID];
    int g = blockIdx.x, t = threadIdx.x;
    float cnt = fmaxf(g_cnt[g], 1.f);
    sm[t] = g_pool[g * HID + t] / cnt;
    __syncthreads();
    if (t < 32) {
        float r = b1[t];
#pragma unroll
        for (int i = 0; i < HID; i++) r += sm[i] * W1[i * 32 + t];
        r = fmaxf(r, 0.f) * W2[t];
#pragma unroll
        for (int o = 16; o; o >>= 1) r += __shfl_down_sync(0xffffffffu, r, o);
        if (t == 0) out[g] = r + b2[0];
    }
}

// ---------------- launch ----------------------------------------------------
extern "C" void kernel_launch(void* const* d_in, const int* in_sizes, int n_in,
                              void* d_out, int out_size) {
    const float* x   = (const float*)d_in[0];
    const int*   ei  = (const int*)d_in[1];
    const float* ea  = (const float*)d_in[2];
    const int*   bat = (const int*)d_in[3];
    const float* Wn  = (const float*)d_in[4];
    const float* bn  = (const float*)d_in[5];
    const float* Wq  = (const float*)d_in[6];
    const float* bq  = (const float*)d_in[7];
    const float* Wk  = (const float*)d_in[8];
    const float* bk  = (const float*)d_in[9];
    const float* Wv  = (const float*)d_in[10];
    const float* bv  = (const float*)d_in[11];
    const float* We  = (const float*)d_in[12];
    const float* Ws  = (const float*)d_in[13];
    const float* bs  = (const float*)d_in[14];
    const float* W1  = (const float*)d_in[15];
    const float* b1  = (const float*)d_in[16];
    const float* W2  = (const float*)d_in[17];
    const float* b2  = (const float*)d_in[18];
    float* out = (float*)d_out;

    const int QKVS_SMEM = (4 * 4096 + 256 + 16 * 68 + 1024) * (int)sizeof(float); // 75008
    cudaFuncSetAttribute(k_qkvs, cudaFuncAttributeMaxDynamicSharedMemorySize, QKVS_SMEM);

    const int NODE_BLOCKS = NN / 16;          // 3125 (exact)
    const int SCAN_BLOCKS = (NN + 255) / 256; // 196
    const int EDGE1T      = EE / 256;         // 6250
    const int EDGE4T      = EE * 4 / 256;     // 25000

    // CSR sort (once per launch, reused by all 3 layers)
    k_zerodeg<<<SCAN_BLOCKS, 256>>>();
    k_hist<<<EDGE1T, 256>>>(ei);
    k_scanA<<<SCAN_BLOCKS, 256>>>();
    k_scanB<<<1, 256>>>(SCAN_BLOCKS);
    k_scanC<<<SCAN_BLOCKS, 256>>>();
    k_scatter<<<EDGE4T, 256>>>(ei, ea);

    k_input<<<NODE_BLOCKS, 256>>>(x, Wn, bn);
    for (int l = 0; l < 3; l++) {
        k_qkvs<<<NODE_BLOCKS, 256, QKVS_SMEM>>>(
            Wq + l * HID * HID, bq + l * HID,
            Wk + l * HID * HID, bk + l * HID,
            Wv + l * HID * HID, bv + l * HID,
            Ws + l * HID * HID, bs + l * HID,
            We + l * EIN * HID);
        k_edge<<<NN / 8, 256>>>(We + l * EIN * HID);
    }
    k_poolzero<<<1, 256>>>();
    k_pool<<<NODE_BLOCKS, 256>>>(bat);
    k_mlp<<<GG, 64>>>(W1, b1, W2, b2, out);
}

// round 14
// speedup vs baseline: 2.8155x; 1.0123x over previous
#include <cuda_runtime.h>
#include <cuda_fp16.h>
#include <math.h>

#define NN 50000
#define EE 1600000
#define GG 64
#define HID 64
#define NH 4
#define CH 16
#define NIN 32
#define EIN 16

// ---------------- scratch (device globals; no allocation allowed) ----------
__device__ __align__(16) float  g_h[NN * HID];
__device__ __align__(16) float  g_q[NN * HID];
__device__ __align__(16) float  g_skip[NN * HID];
__device__ __align__(16) float  g_qe[NN * HID];
__device__ __align__(16) __half g_kvh[(size_t)NN * 128];    // per node: k[64] then v[64], fp16
__device__ __align__(16) __half g_eash[(size_t)EE * EIN];   // ea, dst-sorted, fp16
__device__ int   g_src[EE];
__device__ int   g_deg[NN];
__device__ int   g_off[NN + 1];
__device__ int   g_ctr[NN];
__device__ int   g_part[256];
__device__ int   g_partpre[256];
__device__ __align__(16) float g_pool[GG * HID];
__device__ float g_cnt[GG];

__device__ __forceinline__ void red_add_v4(float* p, float4 v) {
    asm volatile("red.global.add.v4.f32 [%0], {%1,%2,%3,%4};"
                 :: "l"(p), "f"(v.x), "f"(v.y), "f"(v.z), "f"(v.w) : "memory");
}
__device__ __forceinline__ void red_add_f(float* p, float v) {
    asm volatile("red.global.add.f32 [%0], %1;" :: "l"(p), "f"(v) : "memory");
}
__device__ __forceinline__ void fma2(unsigned long long& d,
                                     unsigned long long a, unsigned long long b) {
    asm("fma.rn.f32x2 %0, %1, %2, %0;" : "+l"(d) : "l"(a), "l"(b));
}
__device__ __forceinline__ unsigned long long pack2(float lo, float hi) {
    unsigned long long r;
    asm("mov.b64 %0, {%1, %2};" : "=l"(r) : "f"(lo), "f"(hi));
    return r;
}
__device__ __forceinline__ float unpack_sum(unsigned long long v) {
    float lo, hi;
    asm("mov.b64 {%0, %1}, %2;" : "=f"(lo), "=f"(hi) : "l"(v));
    return lo + hi;
}

// ---------------- input layer: h = relu(x @ Wn + bn) ------------------------
__global__ void k_input(const float* __restrict__ x,
                        const float* __restrict__ Wn,
                        const float* __restrict__ bn) {
    __shared__ float sW[NIN * HID];
    __shared__ float sx[16][NIN + 2];
    __shared__ float sb[HID];
    int t = threadIdx.x;
    for (int i = t; i < NIN * HID; i += 256) sW[i] = Wn[i];
    if (t < HID) sb[t] = bn[t];
    int nb = blockIdx.x * 16;
    for (int i = t; i < 16 * NIN; i += 256) {
        int r = i / NIN, c = i % NIN;
        sx[r][c] = x[(nb + r) * NIN + c];
    }
    __syncthreads();
    int cw = t & 15;
    int r  = t >> 4;
    int n  = nb + r;
    float a0 = sb[cw*4], a1 = sb[cw*4+1], a2 = sb[cw*4+2], a3 = sb[cw*4+3];
#pragma unroll
    for (int i = 0; i < NIN; i++) {
        float hv = sx[r][i];
        float4 w = *(const float4*)&sW[i * HID + cw * 4];
        a0 += hv * w.x; a1 += hv * w.y; a2 += hv * w.z; a3 += hv * w.w;
    }
    float4 o = make_float4(fmaxf(a0,0.f), fmaxf(a1,0.f), fmaxf(a2,0.f), fmaxf(a3,0.f));
    *(float4*)&g_h[n * HID + cw * 4] = o;
}

// ---------------- CSR sort by dst -------------------------------------------
__global__ void k_zerodeg() {
    int i = blockIdx.x * 256 + threadIdx.x;
    if (i < NN) g_deg[i] = 0;
}
__global__ void k_hist(const int* __restrict__ ei) {
    int e = blockIdx.x * 256 + threadIdx.x;
    atomicAdd(&g_deg[ei[EE + e]], 1);
}
__global__ void k_scanA() {
    __shared__ int sp[256];
    int t = threadIdx.x, i = blockIdx.x * 256 + t;
    int d = (i < NN) ? g_deg[i] : 0;
    sp[t] = d; __syncthreads();
    for (int off = 128; off; off >>= 1) {
        if (t < off) sp[t] += sp[t + off];
        __syncthreads();
    }
    if (t == 0) g_part[blockIdx.x] = sp[0];
}
__global__ void k_scanB(int nparts) {
    __shared__ int sp[256];
    int t = threadIdx.x;
    int v = (t < nparts) ? g_part[t] : 0;
    sp[t] = v; __syncthreads();
    for (int off = 1; off < 256; off <<= 1) {
        int u = (t >= off) ? sp[t - off] : 0;
        __syncthreads();
        sp[t] += u;
        __syncthreads();
    }
    g_partpre[t] = sp[t] - v;   // exclusive
}
__global__ void k_scanC() {
    __shared__ int sp[256];
    int t = threadIdx.x, b = blockIdx.x, i = b * 256 + t;
    int d = (i < NN) ? g_deg[i] : 0;
    sp[t] = d; __syncthreads();
    for (int off = 1; off < 256; off <<= 1) {
        int u = (t >= off) ? sp[t - off] : 0;
        __syncthreads();
        sp[t] += u;
        __syncthreads();
    }
    int off0 = g_partpre[b] + sp[t] - d;   // exclusive
    if (i < NN) { g_off[i] = off0; g_ctr[i] = off0; }
    if (b == 0 && t == 0) g_off[NN] = EE;
}
__global__ void k_scatter(const int* __restrict__ ei, const float* __restrict__ ea) {
    long tid = (long)blockIdx.x * 256 + threadIdx.x;
    long e = tid >> 2;
    int  j = (int)(tid & 3);
    int lane = threadIdx.x & 31;
    int pos = 0;
    if (j == 0) {
        int d = ei[EE + e];
        pos = atomicAdd(&g_ctr[d], 1);
        g_src[pos] = ei[e];
    }
    pos = __shfl_sync(0xffffffffu, pos, lane & ~3);
    float4 v = ((const float4*)&ea[(size_t)e * EIN])[j];
    __half2 p0 = __float22half2_rn(make_float2(v.x, v.y));
    __half2 p1 = __float22half2_rn(make_float2(v.z, v.w));
    size_t base = (size_t)pos * EIN + j * 4;
    *(__half2*)&g_eash[base]     = p0;
    *(__half2*)&g_eash[base + 2] = p1;
}

// ---------------- per-layer node linears: q,k,v,skip + qe (fused) -----------
// dyn smem: sW2[4*4096] (i-interleaved pairs) + sb[256] + sh[16*68] + sWe[1024]
__global__ void k_qkvs(const float* __restrict__ Wq, const float* __restrict__ bq,
                       const float* __restrict__ Wk, const float* __restrict__ bk,
                       const float* __restrict__ Wv, const float* __restrict__ bv,
                       const float* __restrict__ Ws, const float* __restrict__ bs,
                       const float* __restrict__ We) {
    extern __shared__ float sm[];
    float* sW2 = sm;                    // 16384 (also aliased as sq later)
    float* sb  = sm + 16384;            // 256
    float* sh  = sm + 16640;            // 16*68
    float* sWe = sm + 17728;            // 1024
    int t = threadIdx.x;
    const float* Wp[4] = {Wq, Wk, Wv, Ws};
    const float* bp[4] = {bq, bk, bv, bs};
#pragma unroll
    for (int a0 = 0; a0 < 4; a0++)
        for (int idx = t; idx < 4096; idx += 256) {
            int i = idx >> 6, c = idx & 63;
            sW2[a0 * 4096 + ((i >> 1) << 7) + (c << 1) + (i & 1)] = Wp[a0][idx];
        }
    sb[t] = bp[t >> 6][t & 63];
    for (int i = t; i < 1024; i += 256) sWe[i] = We[i];
    int nb = blockIdx.x * 16;
    for (int i = t; i < 16 * HID; i += 256) {
        int r = i >> 6, c = i & 63;
        sh[r * 68 + c] = g_h[(nb + r) * HID + c];
    }
    __syncthreads();

    int a  = t >> 6;          // array: 0=q 1=k 2=v 3=skip
    int cw = t & 15;          // 4-col group
    int nq = (t >> 4) & 3;    // 4-node group
    unsigned long long acc2[4][4];
#pragma unroll
    for (int m = 0; m < 4; m++)
#pragma unroll
        for (int c = 0; c < 4; c++)
            acc2[m][c] = pack2(sb[a * 64 + cw * 4 + c], 0.f);
    const float* wbase = &sW2[a * 4096 + cw * 8];
#pragma unroll 4
    for (int i2 = 0; i2 < 32; i2++) {
        ulonglong2 w01 = *(const ulonglong2*)&wbase[i2 * 128];
        ulonglong2 w23 = *(const ulonglong2*)&wbase[i2 * 128 + 4];
#pragma unroll
        for (int m = 0; m < 4; m++) {
            unsigned long long hv =
                *(const unsigned long long*)&sh[(nq * 4 + m) * 68 + i2 * 2];
            fma2(acc2[m][0], hv, w01.x);
            fma2(acc2[m][1], hv, w01.y);
            fma2(acc2[m][2], hv, w23.x);
            fma2(acc2[m][3], hv, w23.y);
        }
    }
    float o[4][4];
#pragma unroll
    for (int m = 0; m < 4; m++)
#pragma unroll
        for (int c = 0; c < 4; c++) o[m][c] = unpack_sum(acc2[m][c]);

    if (a == 1 || a == 2) {
        // k or v -> fp16 interleaved g_kvh (k at 0, v at 64)
        int voff = (a == 2) ? 64 : 0;
#pragma unroll
        for (int m = 0; m < 4; m++) {
            __half2 p0 = __float22half2_rn(make_float2(o[m][0], o[m][1]));
            __half2 p1 = __float22half2_rn(make_float2(o[m][2], o[m][3]));
            __half2* dst = (__half2*)&g_kvh[(size_t)(nb + nq * 4 + m) * 128 + voff + cw * 4];
            dst[0] = p0; dst[1] = p1;
        }
    } else {
        float* outp = (a == 0) ? g_q : g_skip;
#pragma unroll
        for (int m = 0; m < 4; m++)
            *(float4*)&outp[(nb + nq * 4 + m) * HID + cw * 4] =
                make_float4(o[m][0], o[m][1], o[m][2], o[m][3]);
    }
    __syncthreads();
    // stage q into sq (alias sW2[0..1024)) for qe
    float* sq = sm;
    if (a == 0)
#pragma unroll
        for (int m = 0; m < 4; m++)
#pragma unroll
            for (int c = 0; c < 4; c++)
                sq[(nq * 4 + m) * 64 + cw * 4 + c] = o[m][c];
    __syncthreads();
    // qe[n, h*16+i0] = sum_c We[i0, h*16+c] * q[n, h*16+c]
#pragma unroll
    for (int kk = 0; kk < 4; kk++) {
        int oo = t + 256 * kk;
        int r = oo >> 6, j = oo & 63, h = j >> 4, i0 = j & 15;
        float s = 0.f;
#pragma unroll
        for (int c = 0; c < CH; c++)
            s += sWe[i0 * HID + h * CH + c] * sq[r * 64 + h * CH + c];
        g_qe[(nb + r) * HID + j] = s;
    }
}

// ---------------- fused edge pass: online softmax + aggregate + update ------
// warp per dst node; 4 edge-slots (g) x 8 lanes (u). Lane u owns cols
// c0=8u..8u+7, i.e. head h=u>>1, ea-half = u&1.
// BRANCHLESS 2-deep pipeline: all prefetches unconditional with clamped
// indices (safe reads, values discarded by `valid` predicate). The only
// branch in the loop is the back-edge — no BSSY/BSYNC machinery.
__global__ void __launch_bounds__(256, 3) k_edge(const float* __restrict__ We) {
    __shared__ float sWe[EIN * HID];
    __shared__ float s_e[8][4][16];
    __shared__ float s_den[8][4];
    int t = threadIdx.x;
    for (int i = t; i < EIN * HID; i += 256) sWe[i] = We[i];
    __syncthreads();
    int wid = t >> 5, lane = t & 31;
    int n = blockIdx.x * 8 + wid;      // grid = 6250, exact
    int g = lane >> 3, u = lane & 7;
    int h = u >> 1, half = u & 1;
    int c0 = u * 8;                    // owned column range
    int begin = g_off[n], end = g_off[n + 1];
    int nIter = (end - begin + 3) >> 2;   // warp-uniform

    float q[8], qe[8];
    {
        const float4* qp  = (const float4*)&g_q [(size_t)n * HID + c0];
        const float4* qep = (const float4*)&g_qe[(size_t)n * HID + c0];
        float4 a0 = qp[0], a1 = qp[1], b0 = qep[0], b1 = qep[1];
        q[0]=a0.x; q[1]=a0.y; q[2]=a0.z; q[3]=a0.w;
        q[4]=a1.x; q[5]=a1.y; q[6]=a1.z; q[7]=a1.w;
        qe[0]=b0.x; qe[1]=b0.y; qe[2]=b0.z; qe[3]=b0.w;
        qe[4]=b1.x; qe[5]=b1.y; qe[6]=b1.z; qe[7]=b1.w;
    }

    float m = -1e30f, den = 0.f;
    float vacc[8] = {}, eacc[8] = {};

    if (nIter > 0) {
        int last = end - 1;
        // stage 0: src/ea for iter 0, kv for iter 0 (exposed once)
        int pc0 = min(begin + g, last);
        int s0 = g_src[pc0];
        uint4 eaq = __ldcs((const uint4*)&g_eash[(size_t)pc0 * EIN + half * 8]);
        const uint4* kvp0 = (const uint4*)&g_kvh[(size_t)s0 * 128];
        uint4 kh = kvp0[u];
        uint4 vh = kvp0[8 + u];
        // src/ea for iter 1 (clamped, unconditional)
        int pc1 = min(begin + 4 + g, last);
        int s1 = g_src[pc1];
        uint4 ea1 = __ldcs((const uint4*)&g_eash[(size_t)pc1 * EIN + half * 8]);
        for (int it = 0; it < nIter; it++) {
            // kv loads for iter it+1 (unconditional; s1 always valid)
            const uint4* kvp = (const uint4*)&g_kvh[(size_t)s1 * 128];
            uint4 kh_n = kvp[u];
            uint4 vh_n = kvp[8 + u];
            // src/ea for iter it+2 (unconditional, clamped)
            int pc2 = min(begin + (it + 2) * 4 + g, last);
            int s2 = g_src[pc2];
            uint4 ea2 = __ldcs((const uint4*)&g_eash[(size_t)pc2 * EIN + half * 8]);

            int pos = begin + it * 4 + g;
            bool valid = pos < end;
            // convert fp16 -> fp32 (current stage, registers resident)
            float kf[8], vf[8], eaf[8];
            {
                __half2* kp2 = (__half2*)&kh;
                __half2* vp2 = (__half2*)&vh;
                __half2* ep2 = (__half2*)&eaq;
#pragma unroll
                for (int i = 0; i < 4; i++) {
                    float2 kk = __half22float2(kp2[i]);
                    float2 vv = __half22float2(vp2[i]);
                    float2 ee = __half22float2(ep2[i]);
                    kf[i*2] = kk.x; kf[i*2+1] = kk.y;
                    vf[i*2] = vv.x; vf[i*2+1] = vv.y;
                    eaf[i*2] = ee.x; eaf[i*2+1] = ee.y;
                }
            }
            float p = 0.f;
#pragma unroll
            for (int i = 0; i < 8; i++) p += q[i] * kf[i] + qe[i] * eaf[i];
            p += __shfl_xor_sync(0xffffffffu, p, 1);   // combine head halves
            if (valid) {
                float alpha = p * 0.25f;
                float nm = fmaxf(m, alpha);
                float sc = __expf(m - nm);
                float ex = __expf(alpha - nm);
                m = nm;
                den = den * sc + ex;
#pragma unroll
                for (int i = 0; i < 8; i++) {
                    vacc[i] = vacc[i] * sc + ex * vf[i];
                    eacc[i] = eacc[i] * sc + ex * eaf[i];
                }
            }
            kh = kh_n; vh = vh_n; eaq = ea1;
            s1 = s2; ea1 = ea2;
        }
    }

    // merge the 4 edge-slot groups (online-softmax merge)
#pragma unroll
    for (int off = 8; off <= 16; off <<= 1) {
        float m2 = __shfl_xor_sync(0xffffffffu, m, off);
        float d2 = __shfl_xor_sync(0xffffffffu, den, off);
        float nm = fmaxf(m, m2);
        float s1 = __expf(m - nm), s2 = __expf(m2 - nm);
        den = den * s1 + d2 * s2;
#pragma unroll
        for (int i = 0; i < 8; i++) {
            float v2 = __shfl_xor_sync(0xffffffffu, vacc[i], off);
            vacc[i] = vacc[i] * s1 + v2 * s2;
            float e2 = __shfl_xor_sync(0xffffffffu, eacc[i], off);
            eacc[i] = eacc[i] * s1 + e2 * s2;
        }
        m = nm;
    }

    if (g == 0) {
#pragma unroll
        for (int i = 0; i < 8; i++) s_e[wid][h][half * 8 + i] = eacc[i];
        if (half == 0) s_den[wid][h] = den;
    }
    __syncwarp();

    if (g == 0) {
        float inv = 1.f / (s_den[wid][h] + 1e-16f);
        float et[8] = {};
#pragma unroll
        for (int j = 0; j < EIN; j++) {
            float ev = s_e[wid][h][j];
            float4 w0 = *(const float4*)&sWe[j * HID + c0];
            float4 w1 = *(const float4*)&sWe[j * HID + c0 + 4];
            et[0] += ev * w0.x; et[1] += ev * w0.y;
            et[2] += ev * w0.z; et[3] += ev * w0.w;
            et[4] += ev * w1.x; et[5] += ev * w1.y;
            et[6] += ev * w1.z; et[7] += ev * w1.w;
        }
        size_t base = (size_t)n * HID + c0;
        float4 sk0 = *(const float4*)&g_skip[base];
        float4 sk1 = *(const float4*)&g_skip[base + 4];
        float4 hv0 = *(float4*)&g_h[base];
        float4 hv1 = *(float4*)&g_h[base + 4];
        hv0.x += fmaxf((vacc[0] + et[0]) * inv + sk0.x, 0.f);
        hv0.y += fmaxf((vacc[1] + et[1]) * inv + sk0.y, 0.f);
        hv0.z += fmaxf((vacc[2] + et[2]) * inv + sk0.z, 0.f);
        hv0.w += fmaxf((vacc[3] + et[3]) * inv + sk0.w, 0.f);
        hv1.x += fmaxf((vacc[4] + et[4]) * inv + sk1.x, 0.f);
        hv1.y += fmaxf((vacc[5] + et[5]) * inv + sk1.y, 0.f);
        hv1.z += fmaxf((vacc[6] + et[6]) * inv + sk1.z, 0.f);
        hv1.w += fmaxf((vacc[7] + et[7]) * inv + sk1.w, 0.f);
        *(float4*)&g_h[base] = hv0;
        *(float4*)&g_h[base + 4] = hv1;
    }
}

// ---------------- pooling + MLP ---------------------------------------------
__global__ void k_poolzero() {
    int t = threadIdx.x;
    for (int i = t; i < GG * HID; i += 256) g_pool[i] = 0.f;
    if (t < GG) g_cnt[t] = 0.f;
}
__global__ void k_pool(const int* __restrict__ batch) {
    long idx = (long)blockIdx.x * 256 + threadIdx.x;
    int n = (int)(idx >> 4), cg = (int)(idx & 15);
    if (n >= NN) return;
    int b = batch[n];
    float4 hv = *(const float4*)&g_h[n * HID + cg * 4];
    red_add_v4(&g_pool[b * HID + cg * 4], hv);
    if (cg == 0) red_add_f(&g_cnt[b], 1.f);
}
__global__ void k_mlp(const float* __restrict__ W1, const float* __restrict__ b1,
                      const float* __restrict__ W2, const float* __restrict__ b2,
                      float* __restrict__ out) {
    __shared__ float sm[HID];
    int g = blockIdx.x, t = threadIdx.x;
    float cnt = fmaxf(g_cnt[g], 1.f);
    sm[t] = g_pool[g * HID + t] / cnt;
    __syncthreads();
    if (t < 32) {
        float r = b1[t];
#pragma unroll
        for (int i = 0; i < HID; i++) r += sm[i] * W1[i * 32 + t];
        r = fmaxf(r, 0.f) * W2[t];
#pragma unroll
        for (int o = 16; o; o >>= 1) r += __shfl_down_sync(0xffffffffu, r, o);
        if (t == 0) out[g] = r + b2[0];
    }
}

// ---------------- launch ----------------------------------------------------
extern "C" void kernel_launch(void* const* d_in, const int* in_sizes, int n_in,
                              void* d_out, int out_size) {
    const float* x   = (const float*)d_in[0];
    const int*   ei  = (const int*)d_in[1];
    const float* ea  = (const float*)d_in[2];
    const int*   bat = (const int*)d_in[3];
    const float* Wn  = (const float*)d_in[4];
    const float* bn  = (const float*)d_in[5];
    const float* Wq  = (const float*)d_in[6];
    const float* bq  = (const float*)d_in[7];
    const float* Wk  = (const float*)d_in[8];
    const float* bk  = (const float*)d_in[9];
    const float* Wv  = (const float*)d_in[10];
    const float* bv  = (const float*)d_in[11];
    const float* We  = (const float*)d_in[12];
    const float* Ws  = (const float*)d_in[13];
    const float* bs  = (const float*)d_in[14];
    const float* W1  = (const float*)d_in[15];
    const float* b1  = (const float*)d_in[16];
    const float* W2  = (const float*)d_in[17];
    const float* b2  = (const float*)d_in[18];
    float* out = (float*)d_out;

    const int QKVS_SMEM = (4 * 4096 + 256 + 16 * 68 + 1024) * (int)sizeof(float); // 75008
    cudaFuncSetAttribute(k_qkvs, cudaFuncAttributeMaxDynamicSharedMemorySize, QKVS_SMEM);

    const int NODE_BLOCKS = NN / 16;          // 3125 (exact)
    const int SCAN_BLOCKS = (NN + 255) / 256; // 196
    const int EDGE1T      = EE / 256;         // 6250
    const int EDGE4T      = EE * 4 / 256;     // 25000

    // CSR sort (once per launch, reused by all 3 layers)
    k_zerodeg<<<SCAN_BLOCKS, 256>>>();
    k_hist<<<EDGE1T, 256>>>(ei);
    k_scanA<<<SCAN_BLOCKS, 256>>>();
    k_scanB<<<1, 256>>>(SCAN_BLOCKS);
    k_scanC<<<SCAN_BLOCKS, 256>>>();
    k_scatter<<<EDGE4T, 256>>>(ei, ea);

    k_input<<<NODE_BLOCKS, 256>>>(x, Wn, bn);
    for (int l = 0; l < 3; l++) {
        k_qkvs<<<NODE_BLOCKS, 256, QKVS_SMEM>>>(
            Wq + l * HID * HID, bq + l * HID,
            Wk + l * HID * HID, bk + l * HID,
            Wv + l * HID * HID, bv + l * HID,
            Ws + l * HID * HID, bs + l * HID,
            We + l * EIN * HID);
        k_edge<<<NN / 8, 256>>>(We + l * EIN * HID);
    }
    k_poolzero<<<1, 256>>>();
    k_pool<<<NODE_BLOCKS, 256>>>(bat);
    k_mlp<<<GG, 64>>>(W1, b1, W2, b2, out);
}